// round 8
// baseline (speedup 1.0000x reference)
#include <cuda_runtime.h>
#include <math.h>
#include <stdint.h>

#define BATCHN 2
#define SEQ    1024
#define DMODEL 1024
#define DINNER 2048
#define DSTATE 16
#define DCONV  4
#define DTRANK 64
#define MROWS  (BATCHN * SEQ)   // 2048

// ---------------- scratch (device globals; no allocation allowed) -----------
__device__ float g_xz [2][MROWS][2 * DINNER];   // in_proj output
__device__ float g_xi [2][MROWS][DINNER];       // conv+silu output (tf32-pre-rounded)
__device__ float g_dbc[2][MROWS][96];           // x_proj output (tf32-pre-rounded)
__device__ float g_dt [2][MROWS][DINNER];       // softplus(dt)
__device__ float g_y  [2][MROWS][DINNER];       // scan output (tf32-pre-rounded)
__device__ float g_o  [2][MROWS][DMODEL];       // sigmoid(out_proj)
__device__ float g_xpart[16][MROWS * 96];       // x_proj split-K partials
// tf32-pre-rounded operand copies
__device__ float g_rx    [MROWS * DMODEL];
__device__ float g_rw_in [2][2 * DINNER * DMODEL];
__device__ float g_rw_xp [2][96 * DINNER];
__device__ float g_rw_dt [2][DINNER * DTRANK];
__device__ float g_rw_out[2][DMODEL * DINNER];

// pre-round for tf32: truncate(v + 0x1000) == round-half-away(v) for HMMA.TF32.
#define TF32_RND 0x1000u
__device__ __forceinline__ float rnd_tf32(float f) {
    return __uint_as_float(__float_as_uint(f) + TF32_RND);
}

__device__ __forceinline__ void cp16(uint32_t dst, const float* src, int bytes) {
    asm volatile("cp.async.ca.shared.global [%0], [%1], 16, %2;"
                 :: "r"(dst), "l"(src), "r"(bytes));
}
#define CP_COMMIT() asm volatile("cp.async.commit_group;" ::: "memory")

// smem 16B-chunk XOR swizzle: conflict-free for both the cp.async fill and the
// LDS.128 fragment reads (all read rows satisfy row&7 == lq).
__device__ __forceinline__ int swz(int row, int chunk) {
    return chunk ^ ((row & 1) << 2) ^ ((row >> 1) & 3);
}

// ---------------- tf32 tensor-core GEMM (cp.async double-buffered) ----------
//  C[M,N] = A[M,K_chunk] * W[N,K_chunk]^T
// z = dir * nsplit + part; part selects K chunk (split-K); dir selects weights.
// EPI: 0 none, 1 sigmoid, 2 softplus(v+bias[n]);  ROUND: tf32-round output
// reverse_mask bit dir: row m of A maps to (b*SEQ + (SEQ-1-l))
// Operands tf32-pre-rounded. M%128==0, K%32==0, K/32>=2; N ragged OK.
#define GEMM_BM 128
#define GEMM_BN 128
#define GEMM_BK 32
#define GEMM_LDS 32                                   // words per row (128B, swizzled)
#define GEMM_SMEM_BYTES (4 * GEMM_BM * GEMM_LDS * 4)  // 65536

template<int EPI, int ROUND>
__global__ __launch_bounds__(256, 2)
void gemm_mma(const float* __restrict__ A0, size_t strideA,
              const float* __restrict__ W0, const float* __restrict__ W1,
              float* __restrict__ C0, size_t strideC,
              int M, int N, int K, int lda, int ldw, int ldc,
              int reverse_mask, int nsplit,
              const float* __restrict__ bias0, const float* __restrict__ bias1)
{
    constexpr int BM = GEMM_BM, BN = GEMM_BN, BK = GEMM_BK, LDS_S = GEMM_LDS;
    extern __shared__ uint32_t smem[];
    uint32_t* Asb[2] = { smem,                  smem + BM * LDS_S };
    uint32_t* Bsb[2] = { smem + 2 * BM * LDS_S, smem + 2 * BM * LDS_S + BN * LDS_S };

    const int z    = blockIdx.z;
    const int dir  = z / nsplit;
    const int part = z - dir * nsplit;
    const float* A = A0 + (size_t)dir * strideA + (size_t)part * K;
    const float* W = (dir ? W1 : W0) + (size_t)part * K;
    float* C = C0 + (size_t)z * strideC;
    const float* bias = (EPI == 2) ? (dir ? bias1 : bias0) : nullptr;
    const int reverse = (reverse_mask >> dir) & 1;

    const int tid  = threadIdx.x;
    const int lane = tid & 31;
    const int wid  = tid >> 5;
    const int wm   = wid >> 1;
    const int wn   = wid & 1;
    const int m0   = blockIdx.y * BM;
    const int n0   = blockIdx.x * BN;
    const int lq = lane >> 2;
    const int lr = lane & 3;

    const int fr  = tid >> 3;                    // fill row base (0..31)
    const int fc  = tid & 7;                     // fill 16B chunk

    float acc[2][8][4];
#pragma unroll
    for (int i = 0; i < 2; i++)
#pragma unroll
        for (int j = 0; j < 8; j++)
#pragma unroll
            for (int c = 0; c < 4; c++) acc[i][j][c] = 0.f;

    const int KT = K / BK;

    auto fill = [&](int kt, int buf) {
        int k0 = kt * BK;
        uint32_t abuf = (uint32_t)__cvta_generic_to_shared(Asb[buf]);
        uint32_t bbuf = (uint32_t)__cvta_generic_to_shared(Bsb[buf]);
#pragma unroll
        for (int i = 0; i < 4; i++) {
            int r = fr + i * 32;
            uint32_t doff = r * 128 + swz(r, fc) * 16;
            int m = m0 + r;
            int mrow = m;
            if (reverse) mrow = (m & ~(SEQ - 1)) + (SEQ - 1 - (m & (SEQ - 1)));
            cp16(abuf + doff, &A[(size_t)mrow * lda + k0 + fc * 4], 16);
            int n = n0 + r;
            const float* bs = &W[(size_t)(n < N ? n : 0) * ldw + k0 + fc * 4];
            cp16(bbuf + doff, bs, (n < N) ? 16 : 0);
        }
    };

    fill(0, 0);
    CP_COMMIT();

    for (int kt = 0; kt < KT; kt++) {
        const int cur = kt & 1;
        if (kt + 1 < KT) {
            fill(kt + 1, cur ^ 1);
            CP_COMMIT();
            asm volatile("cp.async.wait_group 1;");
        } else {
            asm volatile("cp.async.wait_group 0;");
        }
        __syncthreads();

        const uint32_t* Ac = Asb[cur];
        const uint32_t* Bc = Bsb[cur];
        // k-slot relabeling over each k16 pair of MMAs: thread lr owns words
        // 16g+4lr..+3 (one LDS.128). MMA p of the pair uses words 4lr+2p and
        // 4lr+2p+1. Identical relabeling on A and B -> dot product reordered
        // only (exact same numerics).
#pragma unroll
        for (int g = 0; g < 2; g++) {
            uint4 aw[2][2];
#pragma unroll
            for (int i = 0; i < 2; i++) {
                int r0 = wm * 32 + i * 16 + lq;
                int r1 = r0 + 8;
                aw[i][0] = *reinterpret_cast<const uint4*>(&Ac[r0 * LDS_S + swz(r0, 4 * g + lr) * 4]);
                aw[i][1] = *reinterpret_cast<const uint4*>(&Ac[r1 * LDS_S + swz(r1, 4 * g + lr) * 4]);
            }
#pragma unroll
            for (int j = 0; j < 8; j++) {
                int nr = wn * 64 + j * 8 + lq;
                uint4 bw = *reinterpret_cast<const uint4*>(&Bc[nr * LDS_S + swz(nr, 4 * g + lr) * 4]);
#pragma unroll
                for (int i = 0; i < 2; i++) {
                    asm volatile(
                        "mma.sync.aligned.m16n8k8.row.col.f32.tf32.tf32.f32 "
                        "{%0,%1,%2,%3}, {%4,%5,%6,%7}, {%8,%9}, {%0,%1,%2,%3};"
                        : "+f"(acc[i][j][0]), "+f"(acc[i][j][1]),
                          "+f"(acc[i][j][2]), "+f"(acc[i][j][3])
                        : "r"(aw[i][0].x), "r"(aw[i][1].x),
                          "r"(aw[i][0].y), "r"(aw[i][1].y),
                          "r"(bw.x), "r"(bw.y));
                    asm volatile(
                        "mma.sync.aligned.m16n8k8.row.col.f32.tf32.tf32.f32 "
                        "{%0,%1,%2,%3}, {%4,%5,%6,%7}, {%8,%9}, {%0,%1,%2,%3};"
                        : "+f"(acc[i][j][0]), "+f"(acc[i][j][1]),
                          "+f"(acc[i][j][2]), "+f"(acc[i][j][3])
                        : "r"(aw[i][0].z), "r"(aw[i][1].z),
                          "r"(aw[i][0].w), "r"(aw[i][1].w),
                          "r"(bw.z), "r"(bw.w));
                }
            }
        }
        __syncthreads();
    }

    // ---- epilogue ----
#pragma unroll
    for (int i = 0; i < 2; i++) {
        int mrow0 = m0 + wm * 32 + i * 16 + lq;
#pragma unroll
        for (int j = 0; j < 8; j++) {
            int n = n0 + wn * 64 + j * 8 + lr * 2;
            if (n >= N) continue;
#pragma unroll
            for (int half = 0; half < 2; half++) {
                int m = mrow0 + half * 8;
                float v0 = acc[i][j][half * 2 + 0];
                float v1 = acc[i][j][half * 2 + 1];
                if (EPI == 1) {
                    v0 = 1.f / (1.f + __expf(-v0));
                    v1 = 1.f / (1.f + __expf(-v1));
                } else if (EPI == 2) {
                    v0 += bias[n];
                    v1 += bias[n + 1];
                    v0 = fmaxf(v0, 0.f) + log1pf(__expf(-fabsf(v0)));
                    v1 = fmaxf(v1, 0.f) + log1pf(__expf(-fabsf(v1)));
                }
                if (ROUND) { v0 = rnd_tf32(v0); v1 = rnd_tf32(v1); }
                *reinterpret_cast<float2*>(&C[(size_t)m * ldc + n]) = make_float2(v0, v1);
            }
        }
    }
}

// ---------------- split-K reduction for x_proj ------------------------------
__global__ void reduce_xpart()
{
    int f = blockIdx.x * blockDim.x + threadIdx.x;   // float4 index
    int e = f * 4;
    if (e >= 2 * MROWS * 96) return;
    int dir = e / (MROWS * 96);
    int r   = e - dir * (MROWS * 96);
    float4 acc = make_float4(0.f, 0.f, 0.f, 0.f);
#pragma unroll
    for (int part = 0; part < 8; part++) {
        float4 v = *reinterpret_cast<const float4*>(&g_xpart[dir * 8 + part][r]);
        acc.x += v.x; acc.y += v.y; acc.z += v.z; acc.w += v.w;
    }
    acc.x = rnd_tf32(acc.x); acc.y = rnd_tf32(acc.y);
    acc.z = rnd_tf32(acc.z); acc.w = rnd_tf32(acc.w);
    *reinterpret_cast<float4*>(&g_dbc[dir][0][0] + r) = acc;
}

// ---------------- operand rounding pre-pass ---------------------------------
#define SZ_RX  (MROWS * DMODEL)
#define SZ_IN  (2 * DINNER * DMODEL)
#define SZ_XP  (96 * DINNER)
#define SZ_DT  (DINNER * DTRANK)
#define SZ_OUT (DMODEL * DINNER)
#define RND_TOTAL (SZ_RX + 2*SZ_IN + 2*SZ_XP + 2*SZ_DT + 2*SZ_OUT)

__global__ void round_prepass(const float* __restrict__ x,
                              const float* __restrict__ ip0, const float* __restrict__ ip1,
                              const float* __restrict__ xp0, const float* __restrict__ xp1,
                              const float* __restrict__ dw0, const float* __restrict__ dw1,
                              const float* __restrict__ op0, const float* __restrict__ op1)
{
    long long idx = ((long long)blockIdx.x * blockDim.x + threadIdx.x) * 4;
    const float* src; float* dst; long long off = idx;
    if      (off < SZ_RX)             { src = x;   dst = g_rx; }
    else if ((off -= SZ_RX) < SZ_IN)  { src = ip0; dst = g_rw_in[0]; }
    else if ((off -= SZ_IN) < SZ_IN)  { src = ip1; dst = g_rw_in[1]; }
    else if ((off -= SZ_IN) < SZ_XP)  { src = xp0; dst = g_rw_xp[0]; }
    else if ((off -= SZ_XP) < SZ_XP)  { src = xp1; dst = g_rw_xp[1]; }
    else if ((off -= SZ_XP) < SZ_DT)  { src = dw0; dst = g_rw_dt[0]; }
    else if ((off -= SZ_DT) < SZ_DT)  { src = dw1; dst = g_rw_dt[1]; }
    else if ((off -= SZ_DT) < SZ_OUT) { src = op0; dst = g_rw_out[0]; }
    else if ((off -= SZ_OUT) < SZ_OUT){ src = op1; dst = g_rw_out[1]; }
    else return;
    float4 v = *reinterpret_cast<const float4*>(src + off);
    v.x = rnd_tf32(v.x); v.y = rnd_tf32(v.y);
    v.z = rnd_tf32(v.z); v.w = rnd_tf32(v.w);
    *reinterpret_cast<float4*>(dst + off) = v;
}

// ---------------- depthwise causal conv (k=4) + silu, both dirs -------------
__global__ void conv_silu_kernel(const float* __restrict__ cw0, const float* __restrict__ cb0,
                                 const float* __restrict__ cw1, const float* __restrict__ cb1)
{
    int idx = blockIdx.x * blockDim.x + threadIdx.x;
    if (idx >= 2 * MROWS * DINNER) return;
    int c = idx % DINNER;
    int m = (idx / DINNER) % MROWS;
    int dir = idx / (MROWS * DINNER);
    const float* cw = dir ? cw1 : cw0;
    const float* cb = dir ? cb1 : cb0;
    int l = m & (SEQ - 1);
    int mb = m - l;
    float acc = cb[c];
#pragma unroll
    for (int k = 0; k < DCONV; k++) {
        int ls = l - (DCONV - 1) + k;
        if (ls >= 0) acc = fmaf(g_xz[dir][mb + ls][c], cw[c * DCONV + k], acc);
    }
    g_xi[dir][m][c] = rnd_tf32(acc / (1.f + __expf(-acc)));
}

// ---------------- selective scan: smem-staged chunks ------------------------
// block = 16 channels of one (dir, batch); 256 threads = 16 ch x 16 states.
#define SCH 16
#define SLC 64
#define NCHUNK (SEQ / SLC)
__global__ __launch_bounds__(256)
void scan_kernel(const float* __restrict__ Alog0, const float* __restrict__ D0,
                 const float* __restrict__ Alog1, const float* __restrict__ D1)
{
    __shared__ float sdt[2][SLC * SCH];
    __shared__ float sxi[2][SLC * SCH];
    __shared__ float szt[2][SLC * SCH];
    __shared__ float sbc[2][SLC * 32];
    __shared__ float sy [SLC * SCH];

    const int nCg = DINNER / SCH;                 // 128
    const int bid = blockIdx.x;
    const int dir = bid / (BATCHN * nCg);
    const int rem = bid % (BATCHN * nCg);
    const int b   = rem / nCg;
    const int cg  = rem % nCg;
    const int d0  = cg * SCH;
    const int tid = threadIdx.x;
    const int ch  = tid >> 4;
    const int s   = tid & 15;
    const int d   = d0 + ch;
    const int mbase = b * SEQ;

    const float* Alog = dir ? Alog1 : Alog0;
    const float* Dp   = dir ? D1    : D0;
    const float Aval = -__expf(Alog[d * DSTATE + s]);
    const float Dd   = Dp[d];

    const int ll  = tid >> 2;                     // 0..63
    const int lc4 = (tid & 3) * 4;                // 0,4,8,12

    auto load = [&](int c, int buf) {
        int m = mbase + c * SLC;
        cp16((uint32_t)__cvta_generic_to_shared(&sdt[buf][0]) + tid * 16,
             &g_dt[dir][m + ll][d0 + lc4], 16);
        cp16((uint32_t)__cvta_generic_to_shared(&sxi[buf][0]) + tid * 16,
             &g_xi[dir][m + ll][d0 + lc4], 16);
        cp16((uint32_t)__cvta_generic_to_shared(&szt[buf][0]) + tid * 16,
             &g_xz[dir][m + ll][DINNER + d0 + lc4], 16);
#pragma unroll
        for (int i = 0; i < 2; i++) {
            int f = tid + i * 256;
            int l = f >> 3, c4 = (f & 7) * 4;
            cp16((uint32_t)__cvta_generic_to_shared(&sbc[buf][0]) + f * 16,
                 &g_dbc[dir][m + l][DTRANK + c4], 16);
        }
    };

    load(0, 0); CP_COMMIT();
    load(1, 1); CP_COMMIT();

    float h = 0.f;
    for (int c = 0; c < NCHUNK; c++) {
        const int buf = c & 1;
        if (c + 1 < NCHUNK) asm volatile("cp.async.wait_group 1;");
        else                asm volatile("cp.async.wait_group 0;");
        __syncthreads();

#pragma unroll 4
        for (int l = 0; l < SLC; l++) {
            float dtv = sdt[buf][l * SCH + ch];
            float xiv = sxi[buf][l * SCH + ch];
            float Bv  = sbc[buf][l * 32 + s];
            float Cv  = sbc[buf][l * 32 + 16 + s];
            h = fmaf(__expf(dtv * Aval), h, (dtv * xiv) * Bv);
            float p = h * Cv;
            p += __shfl_xor_sync(0xffffffffu, p, 1);
            p += __shfl_xor_sync(0xffffffffu, p, 2);
            p += __shfl_xor_sync(0xffffffffu, p, 4);
            p += __shfl_xor_sync(0xffffffffu, p, 8);
            if (s == 0) {
                float zv = szt[buf][l * SCH + ch];
                float y = p + xiv * Dd;
                y *= zv / (1.f + __expf(-zv));
                sy[l * SCH + ch] = rnd_tf32(y);
            }
        }
        __syncthreads();

        *reinterpret_cast<float4*>(&g_y[dir][mbase + c * SLC + ll][d0 + lc4]) =
            *reinterpret_cast<const float4*>(&sy[ll * SCH + lc4]);
        if (c + 2 < NCHUNK) { load(c + 2, buf); CP_COMMIT(); }
    }
}

// ---------------- combine + layernorm + residual ----------------------------
__global__ void combine_ln_kernel(const float* __restrict__ x,
                                  const float* __restrict__ lng,
                                  const float* __restrict__ lnb,
                                  float* __restrict__ out)
{
    int row = blockIdx.x;
    int b = row / SEQ, l = row % SEQ;
    int rrev = b * SEQ + (SEQ - 1 - l);
    int tid = threadIdx.x;

    float v[4];
    float sum = 0.f, sq = 0.f;
#pragma unroll
    for (int i = 0; i < 4; i++) {
        int dm = tid + i * 256;
        float dv = 0.5f * (g_o[0][row][dm] + g_o[1][rrev][dm]);
        v[i] = dv;
        sum += dv;
        sq  += dv * dv;
    }
#pragma unroll
    for (int o = 16; o; o >>= 1) {
        sum += __shfl_xor_sync(0xffffffffu, sum, o);
        sq  += __shfl_xor_sync(0xffffffffu, sq,  o);
    }
    __shared__ float ssum[8], ssq[8];
    if ((tid & 31) == 0) { ssum[tid >> 5] = sum; ssq[tid >> 5] = sq; }
    __syncthreads();
    float ts = 0.f, tq = 0.f;
#pragma unroll
    for (int i = 0; i < 8; i++) { ts += ssum[i]; tq += ssq[i]; }
    float mu  = ts * (1.f / DMODEL);
    float var = tq * (1.f / DMODEL) - mu * mu;
    float inv = rsqrtf(var + 1e-5f);
#pragma unroll
    for (int i = 0; i < 4; i++) {
        int dm = tid + i * 256;
        out[(size_t)row * DMODEL + dm] =
            fmaf((v[i] - mu) * inv, lng[dm], lnb[dm]) + x[(size_t)row * DMODEL + dm];
    }
}

// ---------------- launch ----------------------------------------------------
extern "C" void kernel_launch(void* const* d_in, const int* in_sizes, int n_in,
                              void* d_out, int out_size)
{
    const float* x = (const float*)d_in[0];
    const float* in_proj[2] = {(const float*)d_in[1],  (const float*)d_in[10]};
    const float* conv_w [2] = {(const float*)d_in[2],  (const float*)d_in[11]};
    const float* conv_b [2] = {(const float*)d_in[3],  (const float*)d_in[12]};
    const float* x_proj [2] = {(const float*)d_in[4],  (const float*)d_in[13]};
    const float* dt_w   [2] = {(const float*)d_in[5],  (const float*)d_in[14]};
    const float* dt_b   [2] = {(const float*)d_in[6],  (const float*)d_in[15]};
    const float* A_log  [2] = {(const float*)d_in[7],  (const float*)d_in[16]};
    const float* Dp     [2] = {(const float*)d_in[8],  (const float*)d_in[17]};
    const float* out_pr [2] = {(const float*)d_in[9],  (const float*)d_in[18]};
    const float* ln_g = (const float*)d_in[19];
    const float* ln_b = (const float*)d_in[20];
    float* out = (float*)d_out;

    float *p_xz, *p_xi, *p_dbc, *p_dt, *p_y, *p_o, *p_xpart;
    float *p_rx, *p_rin, *p_rxp, *p_rdt, *p_rout;
    cudaGetSymbolAddress((void**)&p_xz,   g_xz);
    cudaGetSymbolAddress((void**)&p_xi,   g_xi);
    cudaGetSymbolAddress((void**)&p_dbc,  g_dbc);
    cudaGetSymbolAddress((void**)&p_dt,   g_dt);
    cudaGetSymbolAddress((void**)&p_y,    g_y);
    cudaGetSymbolAddress((void**)&p_o,    g_o);
    cudaGetSymbolAddress((void**)&p_xpart,g_xpart);
    cudaGetSymbolAddress((void**)&p_rx,   g_rx);
    cudaGetSymbolAddress((void**)&p_rin,  g_rw_in);
    cudaGetSymbolAddress((void**)&p_rxp,  g_rw_xp);
    cudaGetSymbolAddress((void**)&p_rdt,  g_rw_dt);
    cudaGetSymbolAddress((void**)&p_rout, g_rw_out);

    cudaFuncSetAttribute(gemm_mma<0,0>, cudaFuncAttributeMaxDynamicSharedMemorySize, GEMM_SMEM_BYTES);
    cudaFuncSetAttribute(gemm_mma<1,0>, cudaFuncAttributeMaxDynamicSharedMemorySize, GEMM_SMEM_BYTES);
    cudaFuncSetAttribute(gemm_mma<2,0>, cudaFuncAttributeMaxDynamicSharedMemorySize, GEMM_SMEM_BYTES);

    const size_t szXZ  = (size_t)MROWS * 2 * DINNER;
    const size_t szXI  = (size_t)MROWS * DINNER;
    const size_t szO   = (size_t)MROWS * DMODEL;

    // 0) tf32-pre-round x + all GEMM weights
    round_prepass<<<(RND_TOTAL / 4 + 255) / 256, 256>>>(
        x, in_proj[0], in_proj[1], x_proj[0], x_proj[1],
        dt_w[0], dt_w[1], out_pr[0], out_pr[1]);

    // 1) in_proj (both dirs; dir1 reads x time-reversed): [2048 x 4096]
    gemm_mma<0,0><<<dim3(2 * DINNER / 128, MROWS / 128, 2), 256, GEMM_SMEM_BYTES>>>(
        p_rx, 0, p_rin, p_rin + SZ_IN, p_xz, szXZ,
        MROWS, 2 * DINNER, DMODEL, DMODEL, DMODEL, 2 * DINNER,
        /*reverse_mask=*/2, /*nsplit=*/1, nullptr, nullptr);

    // 2) depthwise conv + silu
    conv_silu_kernel<<<(2 * MROWS * DINNER + 255) / 256, 256>>>(
        conv_w[0], conv_b[0], conv_w[1], conv_b[1]);

    // 3) x_proj split-K 8-way: [2048 x 96], K=2048 -> 8 x 256
    gemm_mma<0,0><<<dim3(1, MROWS / 128, 16), 256, GEMM_SMEM_BYTES>>>(
        p_xi, szXI, p_rxp, p_rxp + SZ_XP, p_xpart, (size_t)MROWS * 96,
        MROWS, 96, /*K=*/256, DINNER, DINNER, 96,
        0, /*nsplit=*/8, nullptr, nullptr);
    reduce_xpart<<<(2 * MROWS * 96 / 4 + 255) / 256, 256>>>();

    // 4) dt + softplus (both dirs): [2048 x 2048], K=64 (A = dbc, lda=96)
    gemm_mma<2,0><<<dim3(DINNER / 128, MROWS / 128, 2), 256, GEMM_SMEM_BYTES>>>(
        p_dbc, (size_t)MROWS * 96, p_rdt, p_rdt + SZ_DT, p_dt, szXI,
        MROWS, DINNER, DTRANK, 96, DTRANK, DINNER,
        0, 1, dt_b[0], dt_b[1]);

    // 5) selective scan (smem-staged)
    scan_kernel<<<2 * BATCHN * (DINNER / SCH), 256>>>(
        A_log[0], Dp[0], A_log[1], Dp[1]);

    // 6) out_proj + sigmoid (both dirs): [2048 x 1024]
    gemm_mma<1,0><<<dim3(DMODEL / 128, MROWS / 128, 2), 256, GEMM_SMEM_BYTES>>>(
        p_y, szXI, p_rout, p_rout + SZ_OUT, p_o, szO,
        MROWS, DMODEL, DINNER, DINNER, DINNER, DMODEL,
        0, 1, nullptr, nullptr);

    // 7) combine + layernorm + residual
    combine_ln_kernel<<<MROWS, 256>>>(x, ln_g, ln_b, out);
}

// round 10
// speedup vs baseline: 1.0409x; 1.0409x over previous
#include <cuda_runtime.h>
#include <math.h>
#include <stdint.h>

#define BATCHN 2
#define SEQ    1024
#define DMODEL 1024
#define DINNER 2048
#define DSTATE 16
#define DCONV  4
#define DTRANK 64
#define MROWS  (BATCHN * SEQ)   // 2048

// ---------------- scratch (device globals; no allocation allowed) -----------
__device__ float g_xz [2][MROWS][2 * DINNER];   // in_proj output
__device__ float g_xi [2][MROWS][DINNER];       // conv+silu output (tf32-pre-rounded)
__device__ float g_dbc[2][MROWS][96];           // x_proj output (tf32-pre-rounded)
__device__ float g_dt [2][MROWS][DINNER];       // softplus(dt)
__device__ float g_y  [2][MROWS][DINNER];       // scan output (tf32-pre-rounded)
__device__ float g_o  [2][MROWS][DMODEL];       // sigmoid(out_proj)
__device__ float g_xpart[16][MROWS * 96];       // x_proj split-K partials
// tf32-pre-rounded operand copies
__device__ float g_rx    [MROWS * DMODEL];
__device__ float g_rw_in [2][2 * DINNER * DMODEL];
__device__ float g_rw_xp [2][96 * DINNER];
__device__ float g_rw_dt [2][DINNER * DTRANK];
__device__ float g_rw_out[2][DMODEL * DINNER];

// pre-round for tf32: truncate(v + 0x1000) == round-half-away(v) for HMMA.TF32.
#define TF32_RND 0x1000u
__device__ __forceinline__ float rnd_tf32(float f) {
    return __uint_as_float(__float_as_uint(f) + TF32_RND);
}

__device__ __forceinline__ void cp16(uint32_t dst, const float* src, int bytes) {
    asm volatile("cp.async.ca.shared.global [%0], [%1], 16, %2;"
                 :: "r"(dst), "l"(src), "r"(bytes));
}
#define CP_COMMIT() asm volatile("cp.async.commit_group;" ::: "memory")

// ---------------- tf32 tensor-core GEMM (cp.async double-buffered) ----------
//  C[M,N] = A[M,K_chunk] * W[N,K_chunk]^T
// z = dir * nsplit + part; part selects K chunk (split-K); dir selects weights.
// EPI: 0 none, 1 sigmoid, 2 softplus(v+bias[n]);  ROUND: tf32-round output
// reverse_mask bit dir: row m of A maps to (b*SEQ + (SEQ-1-l))
// Operands tf32-pre-rounded. M%128==0, K%32==0, K/32>=2; N ragged OK.
// Tile 128x64, 256 threads, 3 CTAs/SM (occupancy-optimized).
#define GEMM_BM 128
#define GEMM_BN 64
#define GEMM_BK 32
#define GEMM_LDS 40                               // padded stride: conflict-free LDS.64
#define GEMM_A_WORDS (GEMM_BM * GEMM_LDS)         // 5120
#define GEMM_B_WORDS (GEMM_BN * GEMM_LDS)         // 2560
#define GEMM_SMEM_BYTES ((2 * GEMM_A_WORDS + 2 * GEMM_B_WORDS) * 4)   // 61440

template<int EPI, int ROUND>
__global__ __launch_bounds__(256, 3)
void gemm_mma(const float* __restrict__ A0, size_t strideA,
              const float* __restrict__ W0, const float* __restrict__ W1,
              float* __restrict__ C0, size_t strideC,
              int M, int N, int K, int lda, int ldw, int ldc,
              int reverse_mask, int nsplit,
              const float* __restrict__ bias0, const float* __restrict__ bias1)
{
    constexpr int BM = GEMM_BM, BN = GEMM_BN, BK = GEMM_BK, LDS_S = GEMM_LDS;
    extern __shared__ uint32_t smem[];
    uint32_t* Asb[2] = { smem,                    smem + GEMM_A_WORDS };
    uint32_t* Bsb[2] = { smem + 2 * GEMM_A_WORDS, smem + 2 * GEMM_A_WORDS + GEMM_B_WORDS };

    const int z    = blockIdx.z;
    const int dir  = z / nsplit;
    const int part = z - dir * nsplit;
    const float* A = A0 + (size_t)dir * strideA + (size_t)part * K;
    const float* W = (dir ? W1 : W0) + (size_t)part * K;
    float* C = C0 + (size_t)z * strideC;
    const float* bias = (EPI == 2) ? (dir ? bias1 : bias0) : nullptr;
    const int reverse = (reverse_mask >> dir) & 1;

    const int tid  = threadIdx.x;
    const int lane = tid & 31;
    const int wid  = tid >> 5;
    const int wm   = wid >> 1;                   // 0..3  warp row (32 rows)
    const int wn   = wid & 1;                    // 0..1  warp col (32 cols)
    const int m0   = blockIdx.y * BM;
    const int n0   = blockIdx.x * BN;
    const int lq = lane >> 2;
    const int lr = lane & 3;

    const int fr  = tid >> 3;                    // fill row base (0..31)
    const int fc  = tid & 7;                     // fill 16B chunk

    float acc[2][4][4];
#pragma unroll
    for (int i = 0; i < 2; i++)
#pragma unroll
        for (int j = 0; j < 4; j++)
#pragma unroll
            for (int c = 0; c < 4; c++) acc[i][j][c] = 0.f;

    const int KT = K / BK;

    auto fill = [&](int kt, int buf) {
        int k0 = kt * BK;
        uint32_t abuf = (uint32_t)__cvta_generic_to_shared(Asb[buf]);
        uint32_t bbuf = (uint32_t)__cvta_generic_to_shared(Bsb[buf]);
#pragma unroll
        for (int i = 0; i < 4; i++) {            // A: 128 rows
            int r = fr + i * 32;
            int m = m0 + r;
            int mrow = m;
            if (reverse) mrow = (m & ~(SEQ - 1)) + (SEQ - 1 - (m & (SEQ - 1)));
            cp16(abuf + (r * LDS_S + fc * 4) * 4, &A[(size_t)mrow * lda + k0 + fc * 4], 16);
        }
#pragma unroll
        for (int i = 0; i < 2; i++) {            // B: 64 rows
            int r = fr + i * 32;
            int n = n0 + r;
            const float* bs = &W[(size_t)(n < N ? n : 0) * ldw + k0 + fc * 4];
            cp16(bbuf + (r * LDS_S + fc * 4) * 4, bs, (n < N) ? 16 : 0);
        }
    };

    fill(0, 0);
    CP_COMMIT();

    for (int kt = 0; kt < KT; kt++) {
        const int cur = kt & 1;
        if (kt + 1 < KT) {
            fill(kt + 1, cur ^ 1);
            CP_COMMIT();
            asm volatile("cp.async.wait_group 1;");
        } else {
            asm volatile("cp.async.wait_group 0;");
        }
        __syncthreads();

        const uint32_t* Ac = Asb[cur];
        const uint32_t* Bc = Bsb[cur];
        // k-slot relabeling: slot lr <- logical k 2lr, slot lr+4 <- 2lr+1 for
        // both A and B -> dot product reordered only; pairs adjacent -> LDS.64.
#pragma unroll
        for (int ks = 0; ks < 4; ks++) {
            const int k = ks * 8 + 2 * lr;
            uint2 afp[2][2];
#pragma unroll
            for (int i = 0; i < 2; i++) {
                int mr = wm * 32 + i * 16 + lq;
                afp[i][0] = *reinterpret_cast<const uint2*>(&Ac[ mr      * LDS_S + k]);
                afp[i][1] = *reinterpret_cast<const uint2*>(&Ac[(mr + 8) * LDS_S + k]);
            }
#pragma unroll
            for (int j = 0; j < 4; j++) {
                int nr = wn * 32 + j * 8 + lq;
                uint2 bfp = *reinterpret_cast<const uint2*>(&Bc[nr * LDS_S + k]);
#pragma unroll
                for (int i = 0; i < 2; i++) {
                    asm volatile(
                        "mma.sync.aligned.m16n8k8.row.col.f32.tf32.tf32.f32 "
                        "{%0,%1,%2,%3}, {%4,%5,%6,%7}, {%8,%9}, {%0,%1,%2,%3};"
                        : "+f"(acc[i][j][0]), "+f"(acc[i][j][1]),
                          "+f"(acc[i][j][2]), "+f"(acc[i][j][3])
                        : "r"(afp[i][0].x), "r"(afp[i][1].x),
                          "r"(afp[i][0].y), "r"(afp[i][1].y),
                          "r"(bfp.x), "r"(bfp.y));
                }
            }
        }
        __syncthreads();
    }

    // ---- epilogue ----
#pragma unroll
    for (int i = 0; i < 2; i++) {
        int mrow0 = m0 + wm * 32 + i * 16 + lq;
#pragma unroll
        for (int j = 0; j < 4; j++) {
            int n = n0 + wn * 32 + j * 8 + lr * 2;
            if (n >= N) continue;
#pragma unroll
            for (int half = 0; half < 2; half++) {
                int m = mrow0 + half * 8;
                float v0 = acc[i][j][half * 2 + 0];
                float v1 = acc[i][j][half * 2 + 1];
                if (EPI == 1) {
                    v0 = 1.f / (1.f + __expf(-v0));
                    v1 = 1.f / (1.f + __expf(-v1));
                } else if (EPI == 2) {
                    v0 += bias[n];
                    v1 += bias[n + 1];
                    v0 = fmaxf(v0, 0.f) + log1pf(__expf(-fabsf(v0)));
                    v1 = fmaxf(v1, 0.f) + log1pf(__expf(-fabsf(v1)));
                }
                if (ROUND) { v0 = rnd_tf32(v0); v1 = rnd_tf32(v1); }
                *reinterpret_cast<float2*>(&C[(size_t)m * ldc + n]) = make_float2(v0, v1);
            }
        }
    }
}

// ---------------- split-K reduction for x_proj ------------------------------
__global__ void reduce_xpart()
{
    int f = blockIdx.x * blockDim.x + threadIdx.x;   // float4 index
    int e = f * 4;
    if (e >= 2 * MROWS * 96) return;
    int dir = e / (MROWS * 96);
    int r   = e - dir * (MROWS * 96);
    float4 acc = make_float4(0.f, 0.f, 0.f, 0.f);
#pragma unroll
    for (int part = 0; part < 8; part++) {
        float4 v = *reinterpret_cast<const float4*>(&g_xpart[dir * 8 + part][r]);
        acc.x += v.x; acc.y += v.y; acc.z += v.z; acc.w += v.w;
    }
    acc.x = rnd_tf32(acc.x); acc.y = rnd_tf32(acc.y);
    acc.z = rnd_tf32(acc.z); acc.w = rnd_tf32(acc.w);
    *reinterpret_cast<float4*>(&g_dbc[dir][0][0] + r) = acc;
}

// ---------------- operand rounding pre-pass ---------------------------------
#define SZ_RX  (MROWS * DMODEL)
#define SZ_IN  (2 * DINNER * DMODEL)
#define SZ_XP  (96 * DINNER)
#define SZ_DT  (DINNER * DTRANK)
#define SZ_OUT (DMODEL * DINNER)
#define RND_TOTAL (SZ_RX + 2*SZ_IN + 2*SZ_XP + 2*SZ_DT + 2*SZ_OUT)

__global__ void round_prepass(const float* __restrict__ x,
                              const float* __restrict__ ip0, const float* __restrict__ ip1,
                              const float* __restrict__ xp0, const float* __restrict__ xp1,
                              const float* __restrict__ dw0, const float* __restrict__ dw1,
                              const float* __restrict__ op0, const float* __restrict__ op1)
{
    long long idx = ((long long)blockIdx.x * blockDim.x + threadIdx.x) * 4;
    const float* src; float* dst; long long off = idx;
    if      (off < SZ_RX)             { src = x;   dst = g_rx; }
    else if ((off -= SZ_RX) < SZ_IN)  { src = ip0; dst = g_rw_in[0]; }
    else if ((off -= SZ_IN) < SZ_IN)  { src = ip1; dst = g_rw_in[1]; }
    else if ((off -= SZ_IN) < SZ_XP)  { src = xp0; dst = g_rw_xp[0]; }
    else if ((off -= SZ_XP) < SZ_XP)  { src = xp1; dst = g_rw_xp[1]; }
    else if ((off -= SZ_XP) < SZ_DT)  { src = dw0; dst = g_rw_dt[0]; }
    else if ((off -= SZ_DT) < SZ_DT)  { src = dw1; dst = g_rw_dt[1]; }
    else if ((off -= SZ_DT) < SZ_OUT) { src = op0; dst = g_rw_out[0]; }
    else if ((off -= SZ_OUT) < SZ_OUT){ src = op1; dst = g_rw_out[1]; }
    else return;
    float4 v = *reinterpret_cast<const float4*>(src + off);
    v.x = rnd_tf32(v.x); v.y = rnd_tf32(v.y);
    v.z = rnd_tf32(v.z); v.w = rnd_tf32(v.w);
    *reinterpret_cast<float4*>(dst + off) = v;
}

// ---------------- depthwise causal conv (k=4) + silu, both dirs -------------
__global__ void conv_silu_kernel(const float* __restrict__ cw0, const float* __restrict__ cb0,
                                 const float* __restrict__ cw1, const float* __restrict__ cb1)
{
    int idx = blockIdx.x * blockDim.x + threadIdx.x;
    if (idx >= 2 * MROWS * DINNER) return;
    int c = idx % DINNER;
    int m = (idx / DINNER) % MROWS;
    int dir = idx / (MROWS * DINNER);
    const float* cw = dir ? cw1 : cw0;
    const float* cb = dir ? cb1 : cb0;
    int l = m & (SEQ - 1);
    int mb = m - l;
    float acc = cb[c];
#pragma unroll
    for (int k = 0; k < DCONV; k++) {
        int ls = l - (DCONV - 1) + k;
        if (ls >= 0) acc = fmaf(g_xz[dir][mb + ls][c], cw[c * DCONV + k], acc);
    }
    g_xi[dir][m][c] = rnd_tf32(acc / (1.f + __expf(-acc)));
}

// ---------------- selective scan: smem-staged chunks ------------------------
// block = 16 channels of one (dir, batch); 256 threads = 16 ch x 16 states.
#define SCH 16
#define SLC 64
#define NCHUNK (SEQ / SLC)
__global__ __launch_bounds__(256)
void scan_kernel(const float* __restrict__ Alog0, const float* __restrict__ D0,
                 const float* __restrict__ Alog1, const float* __restrict__ D1)
{
    __shared__ float sdt[2][SLC * SCH];
    __shared__ float sxi[2][SLC * SCH];
    __shared__ float szt[2][SLC * SCH];
    __shared__ float sbc[2][SLC * 32];
    __shared__ float sy [SLC * SCH];

    const int nCg = DINNER / SCH;                 // 128
    const int bid = blockIdx.x;
    const int dir = bid / (BATCHN * nCg);
    const int rem = bid % (BATCHN * nCg);
    const int b   = rem / nCg;
    const int cg  = rem % nCg;
    const int d0  = cg * SCH;
    const int tid = threadIdx.x;
    const int ch  = tid >> 4;
    const int s   = tid & 15;
    const int d   = d0 + ch;
    const int mbase = b * SEQ;

    const float* Alog = dir ? Alog1 : Alog0;
    const float* Dp   = dir ? D1    : D0;
    const float Aval = -__expf(Alog[d * DSTATE + s]);
    const float Dd   = Dp[d];

    const int ll  = tid >> 2;                     // 0..63
    const int lc4 = (tid & 3) * 4;                // 0,4,8,12

    auto load = [&](int c, int buf) {
        int m = mbase + c * SLC;
        cp16((uint32_t)__cvta_generic_to_shared(&sdt[buf][0]) + tid * 16,
             &g_dt[dir][m + ll][d0 + lc4], 16);
        cp16((uint32_t)__cvta_generic_to_shared(&sxi[buf][0]) + tid * 16,
             &g_xi[dir][m + ll][d0 + lc4], 16);
        cp16((uint32_t)__cvta_generic_to_shared(&szt[buf][0]) + tid * 16,
             &g_xz[dir][m + ll][DINNER + d0 + lc4], 16);
#pragma unroll
        for (int i = 0; i < 2; i++) {
            int f = tid + i * 256;
            int l = f >> 3, c4 = (f & 7) * 4;
            cp16((uint32_t)__cvta_generic_to_shared(&sbc[buf][0]) + f * 16,
                 &g_dbc[dir][m + l][DTRANK + c4], 16);
        }
    };

    load(0, 0); CP_COMMIT();
    load(1, 1); CP_COMMIT();

    float h = 0.f;
    for (int c = 0; c < NCHUNK; c++) {
        const int buf = c & 1;
        if (c + 1 < NCHUNK) asm volatile("cp.async.wait_group 1;");
        else                asm volatile("cp.async.wait_group 0;");
        __syncthreads();

#pragma unroll 4
        for (int l = 0; l < SLC; l++) {
            float dtv = sdt[buf][l * SCH + ch];
            float xiv = sxi[buf][l * SCH + ch];
            float Bv  = sbc[buf][l * 32 + s];
            float Cv  = sbc[buf][l * 32 + 16 + s];
            h = fmaf(__expf(dtv * Aval), h, (dtv * xiv) * Bv);
            float p = h * Cv;
            p += __shfl_xor_sync(0xffffffffu, p, 1);
            p += __shfl_xor_sync(0xffffffffu, p, 2);
            p += __shfl_xor_sync(0xffffffffu, p, 4);
            p += __shfl_xor_sync(0xffffffffu, p, 8);
            if (s == 0) {
                float zv = szt[buf][l * SCH + ch];
                float y = p + xiv * Dd;
                y *= zv / (1.f + __expf(-zv));
                sy[l * SCH + ch] = rnd_tf32(y);
            }
        }
        __syncthreads();

        *reinterpret_cast<float4*>(&g_y[dir][mbase + c * SLC + ll][d0 + lc4]) =
            *reinterpret_cast<const float4*>(&sy[ll * SCH + lc4]);
        if (c + 2 < NCHUNK) { load(c + 2, buf); CP_COMMIT(); }
    }
}

// ---------------- combine + layernorm + residual ----------------------------
__global__ void combine_ln_kernel(const float* __restrict__ x,
                                  const float* __restrict__ lng,
                                  const float* __restrict__ lnb,
                                  float* __restrict__ out)
{
    int row = blockIdx.x;
    int b = row / SEQ, l = row % SEQ;
    int rrev = b * SEQ + (SEQ - 1 - l);
    int tid = threadIdx.x;

    float v[4];
    float sum = 0.f, sq = 0.f;
#pragma unroll
    for (int i = 0; i < 4; i++) {
        int dm = tid + i * 256;
        float dv = 0.5f * (g_o[0][row][dm] + g_o[1][rrev][dm]);
        v[i] = dv;
        sum += dv;
        sq  += dv * dv;
    }
#pragma unroll
    for (int o = 16; o; o >>= 1) {
        sum += __shfl_xor_sync(0xffffffffu, sum, o);
        sq  += __shfl_xor_sync(0xffffffffu, sq,  o);
    }
    __shared__ float ssum[8], ssq[8];
    if ((tid & 31) == 0) { ssum[tid >> 5] = sum; ssq[tid >> 5] = sq; }
    __syncthreads();
    float ts = 0.f, tq = 0.f;
#pragma unroll
    for (int i = 0; i < 8; i++) { ts += ssum[i]; tq += ssq[i]; }
    float mu  = ts * (1.f / DMODEL);
    float var = tq * (1.f / DMODEL) - mu * mu;
    float inv = rsqrtf(var + 1e-5f);
#pragma unroll
    for (int i = 0; i < 4; i++) {
        int dm = tid + i * 256;
        out[(size_t)row * DMODEL + dm] =
            fmaf((v[i] - mu) * inv, lng[dm], lnb[dm]) + x[(size_t)row * DMODEL + dm];
    }
}

// ---------------- launch ----------------------------------------------------
extern "C" void kernel_launch(void* const* d_in, const int* in_sizes, int n_in,
                              void* d_out, int out_size)
{
    const float* x = (const float*)d_in[0];
    const float* in_proj[2] = {(const float*)d_in[1],  (const float*)d_in[10]};
    const float* conv_w [2] = {(const float*)d_in[2],  (const float*)d_in[11]};
    const float* conv_b [2] = {(const float*)d_in[3],  (const float*)d_in[12]};
    const float* x_proj [2] = {(const float*)d_in[4],  (const float*)d_in[13]};
    const float* dt_w   [2] = {(const float*)d_in[5],  (const float*)d_in[14]};
    const float* dt_b   [2] = {(const float*)d_in[6],  (const float*)d_in[15]};
    const float* A_log  [2] = {(const float*)d_in[7],  (const float*)d_in[16]};
    const float* Dp     [2] = {(const float*)d_in[8],  (const float*)d_in[17]};
    const float* out_pr [2] = {(const float*)d_in[9],  (const float*)d_in[18]};
    const float* ln_g = (const float*)d_in[19];
    const float* ln_b = (const float*)d_in[20];
    float* out = (float*)d_out;

    float *p_xz, *p_xi, *p_dbc, *p_dt, *p_y, *p_o, *p_xpart;
    float *p_rx, *p_rin, *p_rxp, *p_rdt, *p_rout;
    cudaGetSymbolAddress((void**)&p_xz,   g_xz);
    cudaGetSymbolAddress((void**)&p_xi,   g_xi);
    cudaGetSymbolAddress((void**)&p_dbc,  g_dbc);
    cudaGetSymbolAddress((void**)&p_dt,   g_dt);
    cudaGetSymbolAddress((void**)&p_y,    g_y);
    cudaGetSymbolAddress((void**)&p_o,    g_o);
    cudaGetSymbolAddress((void**)&p_xpart,g_xpart);
    cudaGetSymbolAddress((void**)&p_rx,   g_rx);
    cudaGetSymbolAddress((void**)&p_rin,  g_rw_in);
    cudaGetSymbolAddress((void**)&p_rxp,  g_rw_xp);
    cudaGetSymbolAddress((void**)&p_rdt,  g_rw_dt);
    cudaGetSymbolAddress((void**)&p_rout, g_rw_out);

    cudaFuncSetAttribute(gemm_mma<0,0>, cudaFuncAttributeMaxDynamicSharedMemorySize, GEMM_SMEM_BYTES);
    cudaFuncSetAttribute(gemm_mma<1,0>, cudaFuncAttributeMaxDynamicSharedMemorySize, GEMM_SMEM_BYTES);
    cudaFuncSetAttribute(gemm_mma<2,0>, cudaFuncAttributeMaxDynamicSharedMemorySize, GEMM_SMEM_BYTES);

    const size_t szXZ  = (size_t)MROWS * 2 * DINNER;
    const size_t szXI  = (size_t)MROWS * DINNER;
    const size_t szO   = (size_t)MROWS * DMODEL;

    // 0) tf32-pre-round x + all GEMM weights
    round_prepass<<<(RND_TOTAL / 4 + 255) / 256, 256>>>(
        x, in_proj[0], in_proj[1], x_proj[0], x_proj[1],
        dt_w[0], dt_w[1], out_pr[0], out_pr[1]);

    // 1) in_proj (both dirs; dir1 reads x time-reversed): [2048 x 4096]
    gemm_mma<0,0><<<dim3(2 * DINNER / GEMM_BN, MROWS / GEMM_BM, 2), 256, GEMM_SMEM_BYTES>>>(
        p_rx, 0, p_rin, p_rin + SZ_IN, p_xz, szXZ,
        MROWS, 2 * DINNER, DMODEL, DMODEL, DMODEL, 2 * DINNER,
        /*reverse_mask=*/2, /*nsplit=*/1, nullptr, nullptr);

    // 2) depthwise conv + silu
    conv_silu_kernel<<<(2 * MROWS * DINNER + 255) / 256, 256>>>(
        conv_w[0], conv_b[0], conv_w[1], conv_b[1]);

    // 3) x_proj split-K 8-way: [2048 x 96], K=2048 -> 8 x 256
    gemm_mma<0,0><<<dim3((96 + GEMM_BN - 1) / GEMM_BN, MROWS / GEMM_BM, 16), 256, GEMM_SMEM_BYTES>>>(
        p_xi, szXI, p_rxp, p_rxp + SZ_XP, p_xpart, (size_t)MROWS * 96,
        MROWS, 96, /*K=*/256, DINNER, DINNER, 96,
        0, /*nsplit=*/8, nullptr, nullptr);
    reduce_xpart<<<(2 * MROWS * 96 / 4 + 255) / 256, 256>>>();

    // 4) dt + softplus (both dirs): [2048 x 2048], K=64 (A = dbc, lda=96)
    gemm_mma<2,0><<<dim3(DINNER / GEMM_BN, MROWS / GEMM_BM, 2), 256, GEMM_SMEM_BYTES>>>(
        p_dbc, (size_t)MROWS * 96, p_rdt, p_rdt + SZ_DT, p_dt, szXI,
        MROWS, DINNER, DTRANK, 96, DTRANK, DINNER,
        0, 1, dt_b[0], dt_b[1]);

    // 5) selective scan (smem-staged)
    scan_kernel<<<2 * BATCHN * (DINNER / SCH), 256>>>(
        A_log[0], Dp[0], A_log[1], Dp[1]);

    // 6) out_proj + sigmoid (both dirs): [2048 x 1024]
    gemm_mma<1,0><<<dim3(DMODEL / GEMM_BN, MROWS / GEMM_BM, 2), 256, GEMM_SMEM_BYTES>>>(
        p_y, szXI, p_rout, p_rout + SZ_OUT, p_o, szO,
        MROWS, DMODEL, DINNER, DINNER, DINNER, DMODEL,
        0, 1, nullptr, nullptr);

    // 7) combine + layernorm + residual
    combine_ln_kernel<<<MROWS, 256>>>(x, ln_g, ln_b, out);
}

// round 11
// speedup vs baseline: 1.0492x; 1.0079x over previous
#include <cuda_runtime.h>
#include <math.h>
#include <stdint.h>

#define BATCHN 2
#define SEQ    1024
#define DMODEL 1024
#define DINNER 2048
#define DSTATE 16
#define DCONV  4
#define DTRANK 64
#define MROWS  (BATCHN * SEQ)   // 2048

// ---------------- scratch (device globals; no allocation allowed) -----------
__device__ float g_xz [2][MROWS][2 * DINNER];   // in_proj output
__device__ float g_xi [2][MROWS][DINNER];       // conv+silu output (tf32-pre-rounded)
__device__ float g_dbc[2][MROWS][96];           // x_proj output (tf32-pre-rounded)
__device__ float g_dt [2][MROWS][DINNER];       // softplus(dt)
__device__ float g_y  [2][MROWS][DINNER];       // scan output (tf32-pre-rounded)
__device__ float g_o  [2][MROWS][DMODEL];       // sigmoid(out_proj)
__device__ float g_xpart[16][MROWS * 96];       // x_proj split-K partials
// tf32-pre-rounded operand copies
__device__ float g_rx    [MROWS * DMODEL];
__device__ float g_rw_in [2][2 * DINNER * DMODEL];
__device__ float g_rw_xp [2][96 * DINNER];
__device__ float g_rw_dt [2][DINNER * DTRANK];
__device__ float g_rw_out[2][DMODEL * DINNER];

// pre-round for tf32: truncate(v + 0x1000) == round-half-away(v) for HMMA.TF32.
#define TF32_RND 0x1000u
__device__ __forceinline__ float rnd_tf32(float f) {
    return __uint_as_float(__float_as_uint(f) + TF32_RND);
}

__device__ __forceinline__ void cp16(uint32_t dst, const float* src, int bytes) {
    asm volatile("cp.async.ca.shared.global [%0], [%1], 16, %2;"
                 :: "r"(dst), "l"(src), "r"(bytes));
}
#define CP_COMMIT() asm volatile("cp.async.commit_group;" ::: "memory")

// ---------------- tf32 tensor-core GEMM (cp.async double-buffered) ----------
//  C[M,N] = A[M,K_chunk] * W[N,K_chunk]^T
// z = dir * nsplit + part; part selects K chunk (split-K); dir selects weights.
// EPI: 0 none, 1 sigmoid, 2 softplus(v+bias[n]);  ROUND: tf32-round output
// reverse_mask bit dir: row m of A maps to (b*SEQ + (SEQ-1-l))
// Operands tf32-pre-rounded. M%256==0, K%32==0, K/32>=2; N ragged OK.
// Tile 256x128, 256 threads, warp tile 64x64 (smem-traffic-optimized:
// 0.128 B/MAC fragment traffic vs 0.183 at 128x128/32x64).
#define GEMM_BM 256
#define GEMM_BN 128
#define GEMM_BK 32
#define GEMM_LDS 40                               // padded stride: conflict-free LDS.64
#define GEMM_A_WORDS (GEMM_BM * GEMM_LDS)         // 10240
#define GEMM_B_WORDS (GEMM_BN * GEMM_LDS)         // 5120
#define GEMM_SMEM_BYTES ((2 * GEMM_A_WORDS + 2 * GEMM_B_WORDS) * 4)   // 122880

template<int EPI, int ROUND>
__global__ __launch_bounds__(256, 1)
void gemm_mma(const float* __restrict__ A0, size_t strideA,
              const float* __restrict__ W0, const float* __restrict__ W1,
              float* __restrict__ C0, size_t strideC,
              int M, int N, int K, int lda, int ldw, int ldc,
              int reverse_mask, int nsplit,
              const float* __restrict__ bias0, const float* __restrict__ bias1)
{
    constexpr int LDS_S = GEMM_LDS;
    extern __shared__ uint32_t smem[];
    uint32_t* Asb[2] = { smem,                    smem + GEMM_A_WORDS };
    uint32_t* Bsb[2] = { smem + 2 * GEMM_A_WORDS, smem + 2 * GEMM_A_WORDS + GEMM_B_WORDS };

    const int z    = blockIdx.z;
    const int dir  = z / nsplit;
    const int part = z - dir * nsplit;
    const float* A = A0 + (size_t)dir * strideA + (size_t)part * K;
    const float* W = (dir ? W1 : W0) + (size_t)part * K;
    float* C = C0 + (size_t)z * strideC;
    const float* bias = (EPI == 2) ? (dir ? bias1 : bias0) : nullptr;
    const int reverse = (reverse_mask >> dir) & 1;

    const int tid  = threadIdx.x;
    const int lane = tid & 31;
    const int wid  = tid >> 5;
    const int wm   = wid >> 1;                   // 0..3  warp row (64 rows)
    const int wn   = wid & 1;                    // 0..1  warp col (64 cols)
    const int m0   = blockIdx.y * GEMM_BM;
    const int n0   = blockIdx.x * GEMM_BN;
    const int lq = lane >> 2;
    const int lr = lane & 3;

    const int fr  = tid >> 3;                    // fill row base (0..31)
    const int fc  = tid & 7;                     // fill 16B chunk

    float acc[4][8][4];
#pragma unroll
    for (int i = 0; i < 4; i++)
#pragma unroll
        for (int j = 0; j < 8; j++)
#pragma unroll
            for (int c = 0; c < 4; c++) acc[i][j][c] = 0.f;

    const int KT = K / GEMM_BK;

    auto fill = [&](int kt, int buf) {
        int k0 = kt * GEMM_BK;
        uint32_t abuf = (uint32_t)__cvta_generic_to_shared(Asb[buf]);
        uint32_t bbuf = (uint32_t)__cvta_generic_to_shared(Bsb[buf]);
#pragma unroll
        for (int i = 0; i < 8; i++) {            // A: 256 rows
            int r = fr + i * 32;
            int m = m0 + r;
            int mrow = m;
            if (reverse) mrow = (m & ~(SEQ - 1)) + (SEQ - 1 - (m & (SEQ - 1)));
            cp16(abuf + (r * LDS_S + fc * 4) * 4, &A[(size_t)mrow * lda + k0 + fc * 4], 16);
        }
#pragma unroll
        for (int i = 0; i < 4; i++) {            // B: 128 rows
            int r = fr + i * 32;
            int n = n0 + r;
            const float* bs = &W[(size_t)(n < N ? n : 0) * ldw + k0 + fc * 4];
            cp16(bbuf + (r * LDS_S + fc * 4) * 4, bs, (n < N) ? 16 : 0);
        }
    };

    fill(0, 0);
    CP_COMMIT();

    for (int kt = 0; kt < KT; kt++) {
        const int cur = kt & 1;
        if (kt + 1 < KT) {
            fill(kt + 1, cur ^ 1);
            CP_COMMIT();
            asm volatile("cp.async.wait_group 1;");
        } else {
            asm volatile("cp.async.wait_group 0;");
        }
        __syncthreads();

        const uint32_t* Ac = Asb[cur];
        const uint32_t* Bc = Bsb[cur];
        // k-slot relabeling: slot lr <- logical k 2lr, slot lr+4 <- 2lr+1 for
        // both A and B -> dot product reordered only; pairs adjacent -> LDS.64.
#pragma unroll
        for (int ks = 0; ks < 4; ks++) {
            const int k = ks * 8 + 2 * lr;
            uint2 af[4][2];
#pragma unroll
            for (int i = 0; i < 4; i++) {
                int mr = wm * 64 + i * 16 + lq;
                af[i][0] = *reinterpret_cast<const uint2*>(&Ac[ mr      * LDS_S + k]);
                af[i][1] = *reinterpret_cast<const uint2*>(&Ac[(mr + 8) * LDS_S + k]);
            }
#pragma unroll
            for (int j = 0; j < 8; j++) {
                int nr = wn * 64 + j * 8 + lq;
                uint2 bf = *reinterpret_cast<const uint2*>(&Bc[nr * LDS_S + k]);
#pragma unroll
                for (int i = 0; i < 4; i++) {
                    asm volatile(
                        "mma.sync.aligned.m16n8k8.row.col.f32.tf32.tf32.f32 "
                        "{%0,%1,%2,%3}, {%4,%5,%6,%7}, {%8,%9}, {%0,%1,%2,%3};"
                        : "+f"(acc[i][j][0]), "+f"(acc[i][j][1]),
                          "+f"(acc[i][j][2]), "+f"(acc[i][j][3])
                        : "r"(af[i][0].x), "r"(af[i][1].x),
                          "r"(af[i][0].y), "r"(af[i][1].y),
                          "r"(bf.x), "r"(bf.y));
                }
            }
        }
        __syncthreads();
    }

    // ---- epilogue ----
#pragma unroll
    for (int i = 0; i < 4; i++) {
        int mrow0 = m0 + wm * 64 + i * 16 + lq;
#pragma unroll
        for (int j = 0; j < 8; j++) {
            int n = n0 + wn * 64 + j * 8 + lr * 2;
            if (n >= N) continue;
#pragma unroll
            for (int half = 0; half < 2; half++) {
                int m = mrow0 + half * 8;
                float v0 = acc[i][j][half * 2 + 0];
                float v1 = acc[i][j][half * 2 + 1];
                if (EPI == 1) {
                    v0 = 1.f / (1.f + __expf(-v0));
                    v1 = 1.f / (1.f + __expf(-v1));
                } else if (EPI == 2) {
                    v0 += bias[n];
                    v1 += bias[n + 1];
                    v0 = fmaxf(v0, 0.f) + log1pf(__expf(-fabsf(v0)));
                    v1 = fmaxf(v1, 0.f) + log1pf(__expf(-fabsf(v1)));
                }
                if (ROUND) { v0 = rnd_tf32(v0); v1 = rnd_tf32(v1); }
                *reinterpret_cast<float2*>(&C[(size_t)m * ldc + n]) = make_float2(v0, v1);
            }
        }
    }
}

// ---------------- split-K reduction for x_proj ------------------------------
__global__ void reduce_xpart()
{
    int f = blockIdx.x * blockDim.x + threadIdx.x;   // float4 index
    int e = f * 4;
    if (e >= 2 * MROWS * 96) return;
    int dir = e / (MROWS * 96);
    int r   = e - dir * (MROWS * 96);
    float4 acc = make_float4(0.f, 0.f, 0.f, 0.f);
#pragma unroll
    for (int part = 0; part < 8; part++) {
        float4 v = *reinterpret_cast<const float4*>(&g_xpart[dir * 8 + part][r]);
        acc.x += v.x; acc.y += v.y; acc.z += v.z; acc.w += v.w;
    }
    acc.x = rnd_tf32(acc.x); acc.y = rnd_tf32(acc.y);
    acc.z = rnd_tf32(acc.z); acc.w = rnd_tf32(acc.w);
    *reinterpret_cast<float4*>(&g_dbc[dir][0][0] + r) = acc;
}

// ---------------- operand rounding pre-pass ---------------------------------
#define SZ_RX  (MROWS * DMODEL)
#define SZ_IN  (2 * DINNER * DMODEL)
#define SZ_XP  (96 * DINNER)
#define SZ_DT  (DINNER * DTRANK)
#define SZ_OUT (DMODEL * DINNER)
#define RND_TOTAL (SZ_RX + 2*SZ_IN + 2*SZ_XP + 2*SZ_DT + 2*SZ_OUT)

__global__ void round_prepass(const float* __restrict__ x,
                              const float* __restrict__ ip0, const float* __restrict__ ip1,
                              const float* __restrict__ xp0, const float* __restrict__ xp1,
                              const float* __restrict__ dw0, const float* __restrict__ dw1,
                              const float* __restrict__ op0, const float* __restrict__ op1)
{
    long long idx = ((long long)blockIdx.x * blockDim.x + threadIdx.x) * 4;
    const float* src; float* dst; long long off = idx;
    if      (off < SZ_RX)             { src = x;   dst = g_rx; }
    else if ((off -= SZ_RX) < SZ_IN)  { src = ip0; dst = g_rw_in[0]; }
    else if ((off -= SZ_IN) < SZ_IN)  { src = ip1; dst = g_rw_in[1]; }
    else if ((off -= SZ_IN) < SZ_XP)  { src = xp0; dst = g_rw_xp[0]; }
    else if ((off -= SZ_XP) < SZ_XP)  { src = xp1; dst = g_rw_xp[1]; }
    else if ((off -= SZ_XP) < SZ_DT)  { src = dw0; dst = g_rw_dt[0]; }
    else if ((off -= SZ_DT) < SZ_DT)  { src = dw1; dst = g_rw_dt[1]; }
    else if ((off -= SZ_DT) < SZ_OUT) { src = op0; dst = g_rw_out[0]; }
    else if ((off -= SZ_OUT) < SZ_OUT){ src = op1; dst = g_rw_out[1]; }
    else return;
    float4 v = *reinterpret_cast<const float4*>(src + off);
    v.x = rnd_tf32(v.x); v.y = rnd_tf32(v.y);
    v.z = rnd_tf32(v.z); v.w = rnd_tf32(v.w);
    *reinterpret_cast<float4*>(dst + off) = v;
}

// ---------------- depthwise causal conv (k=4) + silu, both dirs -------------
__global__ void conv_silu_kernel(const float* __restrict__ cw0, const float* __restrict__ cb0,
                                 const float* __restrict__ cw1, const float* __restrict__ cb1)
{
    int idx = blockIdx.x * blockDim.x + threadIdx.x;
    if (idx >= 2 * MROWS * DINNER) return;
    int c = idx % DINNER;
    int m = (idx / DINNER) % MROWS;
    int dir = idx / (MROWS * DINNER);
    const float* cw = dir ? cw1 : cw0;
    const float* cb = dir ? cb1 : cb0;
    int l = m & (SEQ - 1);
    int mb = m - l;
    float acc = cb[c];
#pragma unroll
    for (int k = 0; k < DCONV; k++) {
        int ls = l - (DCONV - 1) + k;
        if (ls >= 0) acc = fmaf(g_xz[dir][mb + ls][c], cw[c * DCONV + k], acc);
    }
    g_xi[dir][m][c] = rnd_tf32(acc / (1.f + __expf(-acc)));
}

// ---------------- selective scan: smem-staged chunks ------------------------
// block = 16 channels of one (dir, batch); 256 threads = 16 ch x 16 states.
#define SCH 16
#define SLC 64
#define NCHUNK (SEQ / SLC)
__global__ __launch_bounds__(256)
void scan_kernel(const float* __restrict__ Alog0, const float* __restrict__ D0,
                 const float* __restrict__ Alog1, const float* __restrict__ D1)
{
    __shared__ float sdt[2][SLC * SCH];
    __shared__ float sxi[2][SLC * SCH];
    __shared__ float szt[2][SLC * SCH];
    __shared__ float sbc[2][SLC * 32];
    __shared__ float sy [SLC * SCH];

    const int nCg = DINNER / SCH;                 // 128
    const int bid = blockIdx.x;
    const int dir = bid / (BATCHN * nCg);
    const int rem = bid % (BATCHN * nCg);
    const int b   = rem / nCg;
    const int cg  = rem % nCg;
    const int d0  = cg * SCH;
    const int tid = threadIdx.x;
    const int ch  = tid >> 4;
    const int s   = tid & 15;
    const int d   = d0 + ch;
    const int mbase = b * SEQ;

    const float* Alog = dir ? Alog1 : Alog0;
    const float* Dp   = dir ? D1    : D0;
    const float Aval = -__expf(Alog[d * DSTATE + s]);
    const float Dd   = Dp[d];

    const int ll  = tid >> 2;                     // 0..63
    const int lc4 = (tid & 3) * 4;                // 0,4,8,12

    auto load = [&](int c, int buf) {
        int m = mbase + c * SLC;
        cp16((uint32_t)__cvta_generic_to_shared(&sdt[buf][0]) + tid * 16,
             &g_dt[dir][m + ll][d0 + lc4], 16);
        cp16((uint32_t)__cvta_generic_to_shared(&sxi[buf][0]) + tid * 16,
             &g_xi[dir][m + ll][d0 + lc4], 16);
        cp16((uint32_t)__cvta_generic_to_shared(&szt[buf][0]) + tid * 16,
             &g_xz[dir][m + ll][DINNER + d0 + lc4], 16);
#pragma unroll
        for (int i = 0; i < 2; i++) {
            int f = tid + i * 256;
            int l = f >> 3, c4 = (f & 7) * 4;
            cp16((uint32_t)__cvta_generic_to_shared(&sbc[buf][0]) + f * 16,
                 &g_dbc[dir][m + l][DTRANK + c4], 16);
        }
    };

    load(0, 0); CP_COMMIT();
    load(1, 1); CP_COMMIT();

    float h = 0.f;
    for (int c = 0; c < NCHUNK; c++) {
        const int buf = c & 1;
        if (c + 1 < NCHUNK) asm volatile("cp.async.wait_group 1;");
        else                asm volatile("cp.async.wait_group 0;");
        __syncthreads();

#pragma unroll 4
        for (int l = 0; l < SLC; l++) {
            float dtv = sdt[buf][l * SCH + ch];
            float xiv = sxi[buf][l * SCH + ch];
            float Bv  = sbc[buf][l * 32 + s];
            float Cv  = sbc[buf][l * 32 + 16 + s];
            h = fmaf(__expf(dtv * Aval), h, (dtv * xiv) * Bv);
            float p = h * Cv;
            p += __shfl_xor_sync(0xffffffffu, p, 1);
            p += __shfl_xor_sync(0xffffffffu, p, 2);
            p += __shfl_xor_sync(0xffffffffu, p, 4);
            p += __shfl_xor_sync(0xffffffffu, p, 8);
            if (s == 0) {
                float zv = szt[buf][l * SCH + ch];
                float y = p + xiv * Dd;
                y *= zv / (1.f + __expf(-zv));
                sy[l * SCH + ch] = rnd_tf32(y);
            }
        }
        __syncthreads();

        *reinterpret_cast<float4*>(&g_y[dir][mbase + c * SLC + ll][d0 + lc4]) =
            *reinterpret_cast<const float4*>(&sy[ll * SCH + lc4]);
        if (c + 2 < NCHUNK) { load(c + 2, buf); CP_COMMIT(); }
    }
}

// ---------------- combine + layernorm + residual ----------------------------
__global__ void combine_ln_kernel(const float* __restrict__ x,
                                  const float* __restrict__ lng,
                                  const float* __restrict__ lnb,
                                  float* __restrict__ out)
{
    int row = blockIdx.x;
    int b = row / SEQ, l = row % SEQ;
    int rrev = b * SEQ + (SEQ - 1 - l);
    int tid = threadIdx.x;

    float v[4];
    float sum = 0.f, sq = 0.f;
#pragma unroll
    for (int i = 0; i < 4; i++) {
        int dm = tid + i * 256;
        float dv = 0.5f * (g_o[0][row][dm] + g_o[1][rrev][dm]);
        v[i] = dv;
        sum += dv;
        sq  += dv * dv;
    }
#pragma unroll
    for (int o = 16; o; o >>= 1) {
        sum += __shfl_xor_sync(0xffffffffu, sum, o);
        sq  += __shfl_xor_sync(0xffffffffu, sq,  o);
    }
    __shared__ float ssum[8], ssq[8];
    if ((tid & 31) == 0) { ssum[tid >> 5] = sum; ssq[tid >> 5] = sq; }
    __syncthreads();
    float ts = 0.f, tq = 0.f;
#pragma unroll
    for (int i = 0; i < 8; i++) { ts += ssum[i]; tq += ssq[i]; }
    float mu  = ts * (1.f / DMODEL);
    float var = tq * (1.f / DMODEL) - mu * mu;
    float inv = rsqrtf(var + 1e-5f);
#pragma unroll
    for (int i = 0; i < 4; i++) {
        int dm = tid + i * 256;
        out[(size_t)row * DMODEL + dm] =
            fmaf((v[i] - mu) * inv, lng[dm], lnb[dm]) + x[(size_t)row * DMODEL + dm];
    }
}

// ---------------- launch ----------------------------------------------------
extern "C" void kernel_launch(void* const* d_in, const int* in_sizes, int n_in,
                              void* d_out, int out_size)
{
    const float* x = (const float*)d_in[0];
    const float* in_proj[2] = {(const float*)d_in[1],  (const float*)d_in[10]};
    const float* conv_w [2] = {(const float*)d_in[2],  (const float*)d_in[11]};
    const float* conv_b [2] = {(const float*)d_in[3],  (const float*)d_in[12]};
    const float* x_proj [2] = {(const float*)d_in[4],  (const float*)d_in[13]};
    const float* dt_w   [2] = {(const float*)d_in[5],  (const float*)d_in[14]};
    const float* dt_b   [2] = {(const float*)d_in[6],  (const float*)d_in[15]};
    const float* A_log  [2] = {(const float*)d_in[7],  (const float*)d_in[16]};
    const float* Dp     [2] = {(const float*)d_in[8],  (const float*)d_in[17]};
    const float* out_pr [2] = {(const float*)d_in[9],  (const float*)d_in[18]};
    const float* ln_g = (const float*)d_in[19];
    const float* ln_b = (const float*)d_in[20];
    float* out = (float*)d_out;

    float *p_xz, *p_xi, *p_dbc, *p_dt, *p_y, *p_o, *p_xpart;
    float *p_rx, *p_rin, *p_rxp, *p_rdt, *p_rout;
    cudaGetSymbolAddress((void**)&p_xz,   g_xz);
    cudaGetSymbolAddress((void**)&p_xi,   g_xi);
    cudaGetSymbolAddress((void**)&p_dbc,  g_dbc);
    cudaGetSymbolAddress((void**)&p_dt,   g_dt);
    cudaGetSymbolAddress((void**)&p_y,    g_y);
    cudaGetSymbolAddress((void**)&p_o,    g_o);
    cudaGetSymbolAddress((void**)&p_xpart,g_xpart);
    cudaGetSymbolAddress((void**)&p_rx,   g_rx);
    cudaGetSymbolAddress((void**)&p_rin,  g_rw_in);
    cudaGetSymbolAddress((void**)&p_rxp,  g_rw_xp);
    cudaGetSymbolAddress((void**)&p_rdt,  g_rw_dt);
    cudaGetSymbolAddress((void**)&p_rout, g_rw_out);

    cudaFuncSetAttribute(gemm_mma<0,0>, cudaFuncAttributeMaxDynamicSharedMemorySize, GEMM_SMEM_BYTES);
    cudaFuncSetAttribute(gemm_mma<1,0>, cudaFuncAttributeMaxDynamicSharedMemorySize, GEMM_SMEM_BYTES);
    cudaFuncSetAttribute(gemm_mma<2,0>, cudaFuncAttributeMaxDynamicSharedMemorySize, GEMM_SMEM_BYTES);

    const size_t szXZ  = (size_t)MROWS * 2 * DINNER;
    const size_t szXI  = (size_t)MROWS * DINNER;
    const size_t szO   = (size_t)MROWS * DMODEL;

    // 0) tf32-pre-round x + all GEMM weights
    round_prepass<<<(RND_TOTAL / 4 + 255) / 256, 256>>>(
        x, in_proj[0], in_proj[1], x_proj[0], x_proj[1],
        dt_w[0], dt_w[1], out_pr[0], out_pr[1]);

    // 1) in_proj (both dirs; dir1 reads x time-reversed): [2048 x 4096]
    gemm_mma<0,0><<<dim3(2 * DINNER / GEMM_BN, MROWS / GEMM_BM, 2), 256, GEMM_SMEM_BYTES>>>(
        p_rx, 0, p_rin, p_rin + SZ_IN, p_xz, szXZ,
        MROWS, 2 * DINNER, DMODEL, DMODEL, DMODEL, 2 * DINNER,
        /*reverse_mask=*/2, /*nsplit=*/1, nullptr, nullptr);

    // 2) depthwise conv + silu
    conv_silu_kernel<<<(2 * MROWS * DINNER + 255) / 256, 256>>>(
        conv_w[0], conv_b[0], conv_w[1], conv_b[1]);

    // 3) x_proj split-K 8-way: [2048 x 96], K=2048 -> 8 x 256
    gemm_mma<0,0><<<dim3(1, MROWS / GEMM_BM, 16), 256, GEMM_SMEM_BYTES>>>(
        p_xi, szXI, p_rxp, p_rxp + SZ_XP, p_xpart, (size_t)MROWS * 96,
        MROWS, 96, /*K=*/256, DINNER, DINNER, 96,
        0, /*nsplit=*/8, nullptr, nullptr);
    reduce_xpart<<<(2 * MROWS * 96 / 4 + 255) / 256, 256>>>();

    // 4) dt + softplus (both dirs): [2048 x 2048], K=64 (A = dbc, lda=96)
    gemm_mma<2,0><<<dim3(DINNER / GEMM_BN, MROWS / GEMM_BM, 2), 256, GEMM_SMEM_BYTES>>>(
        p_dbc, (size_t)MROWS * 96, p_rdt, p_rdt + SZ_DT, p_dt, szXI,
        MROWS, DINNER, DTRANK, 96, DTRANK, DINNER,
        0, 1, dt_b[0], dt_b[1]);

    // 5) selective scan (smem-staged)
    scan_kernel<<<2 * BATCHN * (DINNER / SCH), 256>>>(
        A_log[0], Dp[0], A_log[1], Dp[1]);

    // 6) out_proj + sigmoid (both dirs): [2048 x 1024]
    gemm_mma<1,0><<<dim3(DMODEL / GEMM_BN, MROWS / GEMM_BM, 2), 256, GEMM_SMEM_BYTES>>>(
        p_y, szXI, p_rout, p_rout + SZ_OUT, p_o, szO,
        MROWS, DMODEL, DINNER, DINNER, DINNER, DMODEL,
        0, 1, nullptr, nullptr);

    // 7) combine + layernorm + residual
    combine_ln_kernel<<<MROWS, 256>>>(x, ln_g, ln_b, out);
}

// round 12
// speedup vs baseline: 1.0916x; 1.0405x over previous
#include <cuda_runtime.h>
#include <math.h>
#include <stdint.h>

#define BATCHN 2
#define SEQ    1024
#define DMODEL 1024
#define DINNER 2048
#define DSTATE 16
#define DCONV  4
#define DTRANK 64
#define MROWS  (BATCHN * SEQ)   // 2048

// ---------------- scratch (device globals; no allocation allowed) -----------
__device__ float g_xz [2][MROWS][2 * DINNER];   // in_proj output
__device__ float g_xi [2][MROWS][DINNER];       // conv+silu output (tf32-pre-rounded)
__device__ float g_dbc[2][MROWS][96];           // x_proj output (tf32-pre-rounded)
__device__ float g_dt [2][MROWS][DINNER];       // softplus(dt)
__device__ float g_y  [2][MROWS][DINNER];       // scan output (tf32-pre-rounded)
__device__ float g_o  [2][MROWS][DMODEL];       // sigmoid(out_proj)
__device__ float g_xpart[16][MROWS * 96];       // x_proj split-K partials
// tf32-pre-rounded operand copies
__device__ float g_rx    [MROWS * DMODEL];
__device__ float g_rw_in [2][2 * DINNER * DMODEL];
__device__ float g_rw_xp [2][96 * DINNER];
__device__ float g_rw_dt [2][DINNER * DTRANK];
__device__ float g_rw_out[2][DMODEL * DINNER];

// pre-round for tf32: truncate(v + 0x1000) == round-half-away(v) for HMMA.TF32.
#define TF32_RND 0x1000u
__device__ __forceinline__ float rnd_tf32(float f) {
    return __uint_as_float(__float_as_uint(f) + TF32_RND);
}

__device__ __forceinline__ void cp16(uint32_t dst, const float* src, int bytes) {
    asm volatile("cp.async.ca.shared.global [%0], [%1], 16, %2;"
                 :: "r"(dst), "l"(src), "r"(bytes));
}
#define CP_COMMIT() asm volatile("cp.async.commit_group;" ::: "memory")

// ---------------- tf32 tensor-core GEMM (cp.async double-buffered) ----------
//  C[M,N] = A[M,K_chunk] * W[N,K_chunk]^T
// MI: warp-tile M in units of 16 (MI=2 -> CTA 128x128 (2 CTAs/SM), MI=4 ->
// CTA 256x128 (1 CTA/SM, 0.122 B/MAC fragment traffic for the smem-crossbar
// bound)). z = dir*nsplit+part (split-K). EPI: 0 none, 1 sigmoid,
// 2 softplus(v+bias[n]); ROUND: tf32-round output.
// reverse_mask bit dir: row m of A maps to (b*SEQ + (SEQ-1-l)).
// Operands tf32-pre-rounded. M%(MI*64)==0, K%32==0, K/32>=2; N ragged OK.
#define GEMM_BN 128
#define GEMM_BK 32
#define GEMM_LDS 40                               // padded stride: conflict-free LDS.64
#define GEMM_SMEM(MI) ((2 * (MI * 64) * GEMM_LDS + 2 * GEMM_BN * GEMM_LDS) * 4)

template<int MI, int EPI, int ROUND>
__global__ __launch_bounds__(256, (MI == 2) ? 2 : 1)
void gemm_mma(const float* __restrict__ A0, size_t strideA,
              const float* __restrict__ W0, const float* __restrict__ W1,
              float* __restrict__ C0, size_t strideC,
              int M, int N, int K, int lda, int ldw, int ldc,
              int reverse_mask, int nsplit,
              const float* __restrict__ bias0, const float* __restrict__ bias1)
{
    constexpr int BM = MI * 64;
    constexpr int LDS_S = GEMM_LDS;
    constexpr int A_WORDS = BM * LDS_S;
    constexpr int B_WORDS = GEMM_BN * LDS_S;
    extern __shared__ uint32_t smem[];
    uint32_t* Asb[2] = { smem,               smem + A_WORDS };
    uint32_t* Bsb[2] = { smem + 2 * A_WORDS, smem + 2 * A_WORDS + B_WORDS };

    const int z    = blockIdx.z;
    const int dir  = z / nsplit;
    const int part = z - dir * nsplit;
    const float* A = A0 + (size_t)dir * strideA + (size_t)part * K;
    const float* W = (dir ? W1 : W0) + (size_t)part * K;
    float* C = C0 + (size_t)z * strideC;
    const float* bias = (EPI == 2) ? (dir ? bias1 : bias0) : nullptr;
    const int reverse = (reverse_mask >> dir) & 1;

    const int tid  = threadIdx.x;
    const int lane = tid & 31;
    const int wid  = tid >> 5;
    const int wm   = wid >> 1;                   // 0..3  warp row (MI*16 rows)
    const int wn   = wid & 1;                    // 0..1  warp col (64 cols)
    const int m0   = blockIdx.y * BM;
    const int n0   = blockIdx.x * GEMM_BN;
    const int lq = lane >> 2;
    const int lr = lane & 3;

    const int fr  = tid >> 3;                    // fill row base (0..31)
    const int fc  = tid & 7;                     // fill 16B chunk

    float acc[MI][8][4];
#pragma unroll
    for (int i = 0; i < MI; i++)
#pragma unroll
        for (int j = 0; j < 8; j++)
#pragma unroll
            for (int c = 0; c < 4; c++) acc[i][j][c] = 0.f;

    const int KT = K / GEMM_BK;

    auto fill = [&](int kt, int buf) {
        int k0 = kt * GEMM_BK;
        uint32_t abuf = (uint32_t)__cvta_generic_to_shared(Asb[buf]);
        uint32_t bbuf = (uint32_t)__cvta_generic_to_shared(Bsb[buf]);
#pragma unroll
        for (int i = 0; i < 2 * MI; i++) {       // A: BM rows
            int r = fr + i * 32;
            int m = m0 + r;
            int mrow = m;
            if (reverse) mrow = (m & ~(SEQ - 1)) + (SEQ - 1 - (m & (SEQ - 1)));
            cp16(abuf + (r * LDS_S + fc * 4) * 4, &A[(size_t)mrow * lda + k0 + fc * 4], 16);
        }
#pragma unroll
        for (int i = 0; i < 4; i++) {            // B: 128 rows
            int r = fr + i * 32;
            int n = n0 + r;
            const float* bs = &W[(size_t)(n < N ? n : 0) * ldw + k0 + fc * 4];
            cp16(bbuf + (r * LDS_S + fc * 4) * 4, bs, (n < N) ? 16 : 0);
        }
    };

    fill(0, 0);
    CP_COMMIT();

    for (int kt = 0; kt < KT; kt++) {
        const int cur = kt & 1;
        // single-sync mainloop: wait for tile kt's data, one barrier, then
        // prefetch kt+1 into the buffer whose readers (mma kt-1) the barrier
        // just ordered, then run mma overlapped with the prefetch.
        asm volatile("cp.async.wait_group 0;");
        __syncthreads();
        if (kt + 1 < KT) {
            fill(kt + 1, cur ^ 1);
            CP_COMMIT();
        }

        const uint32_t* Ac = Asb[cur];
        const uint32_t* Bc = Bsb[cur];
        // k-slot relabeling: slot lr <- logical k 2lr, slot lr+4 <- 2lr+1 for
        // both A and B -> dot product reordered only; pairs adjacent -> LDS.64.
#pragma unroll
        for (int ks = 0; ks < 4; ks++) {
            const int k = ks * 8 + 2 * lr;
            uint2 af[MI][2];
#pragma unroll
            for (int i = 0; i < MI; i++) {
                int mr = wm * (16 * MI) + i * 16 + lq;
                af[i][0] = *reinterpret_cast<const uint2*>(&Ac[ mr      * LDS_S + k]);
                af[i][1] = *reinterpret_cast<const uint2*>(&Ac[(mr + 8) * LDS_S + k]);
            }
#pragma unroll
            for (int j = 0; j < 8; j++) {
                int nr = wn * 64 + j * 8 + lq;
                uint2 bf = *reinterpret_cast<const uint2*>(&Bc[nr * LDS_S + k]);
#pragma unroll
                for (int i = 0; i < MI; i++) {
                    asm volatile(
                        "mma.sync.aligned.m16n8k8.row.col.f32.tf32.tf32.f32 "
                        "{%0,%1,%2,%3}, {%4,%5,%6,%7}, {%8,%9}, {%0,%1,%2,%3};"
                        : "+f"(acc[i][j][0]), "+f"(acc[i][j][1]),
                          "+f"(acc[i][j][2]), "+f"(acc[i][j][3])
                        : "r"(af[i][0].x), "r"(af[i][1].x),
                          "r"(af[i][0].y), "r"(af[i][1].y),
                          "r"(bf.x), "r"(bf.y));
                }
            }
        }
    }

    // ---- epilogue ----
#pragma unroll
    for (int i = 0; i < MI; i++) {
        int mrow0 = m0 + wm * (16 * MI) + i * 16 + lq;
#pragma unroll
        for (int j = 0; j < 8; j++) {
            int n = n0 + wn * 64 + j * 8 + lr * 2;
            if (n >= N) continue;
#pragma unroll
            for (int half = 0; half < 2; half++) {
                int m = mrow0 + half * 8;
                float v0 = acc[i][j][half * 2 + 0];
                float v1 = acc[i][j][half * 2 + 1];
                if (EPI == 1) {
                    v0 = 1.f / (1.f + __expf(-v0));
                    v1 = 1.f / (1.f + __expf(-v1));
                } else if (EPI == 2) {
                    v0 += bias[n];
                    v1 += bias[n + 1];
                    v0 = fmaxf(v0, 0.f) + log1pf(__expf(-fabsf(v0)));
                    v1 = fmaxf(v1, 0.f) + log1pf(__expf(-fabsf(v1)));
                }
                if (ROUND) { v0 = rnd_tf32(v0); v1 = rnd_tf32(v1); }
                *reinterpret_cast<float2*>(&C[(size_t)m * ldc + n]) = make_float2(v0, v1);
            }
        }
    }
}

// ---------------- split-K reduction for x_proj ------------------------------
__global__ void reduce_xpart()
{
    int f = blockIdx.x * blockDim.x + threadIdx.x;   // float4 index
    int e = f * 4;
    if (e >= 2 * MROWS * 96) return;
    int dir = e / (MROWS * 96);
    int r   = e - dir * (MROWS * 96);
    float4 acc = make_float4(0.f, 0.f, 0.f, 0.f);
#pragma unroll
    for (int part = 0; part < 8; part++) {
        float4 v = *reinterpret_cast<const float4*>(&g_xpart[dir * 8 + part][r]);
        acc.x += v.x; acc.y += v.y; acc.z += v.z; acc.w += v.w;
    }
    acc.x = rnd_tf32(acc.x); acc.y = rnd_tf32(acc.y);
    acc.z = rnd_tf32(acc.z); acc.w = rnd_tf32(acc.w);
    *reinterpret_cast<float4*>(&g_dbc[dir][0][0] + r) = acc;
}

// ---------------- operand rounding pre-pass ---------------------------------
#define SZ_RX  (MROWS * DMODEL)
#define SZ_IN  (2 * DINNER * DMODEL)
#define SZ_XP  (96 * DINNER)
#define SZ_DT  (DINNER * DTRANK)
#define SZ_OUT (DMODEL * DINNER)
#define RND_TOTAL (SZ_RX + 2*SZ_IN + 2*SZ_XP + 2*SZ_DT + 2*SZ_OUT)

__global__ void round_prepass(const float* __restrict__ x,
                              const float* __restrict__ ip0, const float* __restrict__ ip1,
                              const float* __restrict__ xp0, const float* __restrict__ xp1,
                              const float* __restrict__ dw0, const float* __restrict__ dw1,
                              const float* __restrict__ op0, const float* __restrict__ op1)
{
    long long idx = ((long long)blockIdx.x * blockDim.x + threadIdx.x) * 4;
    const float* src; float* dst; long long off = idx;
    if      (off < SZ_RX)             { src = x;   dst = g_rx; }
    else if ((off -= SZ_RX) < SZ_IN)  { src = ip0; dst = g_rw_in[0]; }
    else if ((off -= SZ_IN) < SZ_IN)  { src = ip1; dst = g_rw_in[1]; }
    else if ((off -= SZ_IN) < SZ_XP)  { src = xp0; dst = g_rw_xp[0]; }
    else if ((off -= SZ_XP) < SZ_XP)  { src = xp1; dst = g_rw_xp[1]; }
    else if ((off -= SZ_XP) < SZ_DT)  { src = dw0; dst = g_rw_dt[0]; }
    else if ((off -= SZ_DT) < SZ_DT)  { src = dw1; dst = g_rw_dt[1]; }
    else if ((off -= SZ_DT) < SZ_OUT) { src = op0; dst = g_rw_out[0]; }
    else if ((off -= SZ_OUT) < SZ_OUT){ src = op1; dst = g_rw_out[1]; }
    else return;
    float4 v = *reinterpret_cast<const float4*>(src + off);
    v.x = rnd_tf32(v.x); v.y = rnd_tf32(v.y);
    v.z = rnd_tf32(v.z); v.w = rnd_tf32(v.w);
    *reinterpret_cast<float4*>(dst + off) = v;
}

// ---------------- depthwise causal conv (k=4) + silu, both dirs -------------
__global__ void conv_silu_kernel(const float* __restrict__ cw0, const float* __restrict__ cb0,
                                 const float* __restrict__ cw1, const float* __restrict__ cb1)
{
    int idx = blockIdx.x * blockDim.x + threadIdx.x;
    if (idx >= 2 * MROWS * DINNER) return;
    int c = idx % DINNER;
    int m = (idx / DINNER) % MROWS;
    int dir = idx / (MROWS * DINNER);
    const float* cw = dir ? cw1 : cw0;
    const float* cb = dir ? cb1 : cb0;
    int l = m & (SEQ - 1);
    int mb = m - l;
    float acc = cb[c];
#pragma unroll
    for (int k = 0; k < DCONV; k++) {
        int ls = l - (DCONV - 1) + k;
        if (ls >= 0) acc = fmaf(g_xz[dir][mb + ls][c], cw[c * DCONV + k], acc);
    }
    g_xi[dir][m][c] = rnd_tf32(acc / (1.f + __expf(-acc)));
}

// ---------------- selective scan: smem-staged chunks ------------------------
// block = 16 channels of one (dir, batch); 256 threads = 16 ch x 16 states.
#define SCH 16
#define SLC 64
#define NCHUNK (SEQ / SLC)
__global__ __launch_bounds__(256)
void scan_kernel(const float* __restrict__ Alog0, const float* __restrict__ D0,
                 const float* __restrict__ Alog1, const float* __restrict__ D1)
{
    __shared__ float sdt[2][SLC * SCH];
    __shared__ float sxi[2][SLC * SCH];
    __shared__ float szt[2][SLC * SCH];
    __shared__ float sbc[2][SLC * 32];
    __shared__ float sy [SLC * SCH];

    const int nCg = DINNER / SCH;                 // 128
    const int bid = blockIdx.x;
    const int dir = bid / (BATCHN * nCg);
    const int rem = bid % (BATCHN * nCg);
    const int b   = rem / nCg;
    const int cg  = rem % nCg;
    const int d0  = cg * SCH;
    const int tid = threadIdx.x;
    const int ch  = tid >> 4;
    const int s   = tid & 15;
    const int d   = d0 + ch;
    const int mbase = b * SEQ;

    const float* Alog = dir ? Alog1 : Alog0;
    const float* Dp   = dir ? D1    : D0;
    const float Aval = -__expf(Alog[d * DSTATE + s]);
    const float Dd   = Dp[d];

    const int ll  = tid >> 2;                     // 0..63
    const int lc4 = (tid & 3) * 4;                // 0,4,8,12

    auto load = [&](int c, int buf) {
        int m = mbase + c * SLC;
        cp16((uint32_t)__cvta_generic_to_shared(&sdt[buf][0]) + tid * 16,
             &g_dt[dir][m + ll][d0 + lc4], 16);
        cp16((uint32_t)__cvta_generic_to_shared(&sxi[buf][0]) + tid * 16,
             &g_xi[dir][m + ll][d0 + lc4], 16);
        cp16((uint32_t)__cvta_generic_to_shared(&szt[buf][0]) + tid * 16,
             &g_xz[dir][m + ll][DINNER + d0 + lc4], 16);
#pragma unroll
        for (int i = 0; i < 2; i++) {
            int f = tid + i * 256;
            int l = f >> 3, c4 = (f & 7) * 4;
            cp16((uint32_t)__cvta_generic_to_shared(&sbc[buf][0]) + f * 16,
                 &g_dbc[dir][m + l][DTRANK + c4], 16);
        }
    };

    load(0, 0); CP_COMMIT();
    load(1, 1); CP_COMMIT();

    float h = 0.f;
    for (int c = 0; c < NCHUNK; c++) {
        const int buf = c & 1;
        if (c + 1 < NCHUNK) asm volatile("cp.async.wait_group 1;");
        else                asm volatile("cp.async.wait_group 0;");
        __syncthreads();

#pragma unroll 4
        for (int l = 0; l < SLC; l++) {
            float dtv = sdt[buf][l * SCH + ch];
            float xiv = sxi[buf][l * SCH + ch];
            float Bv  = sbc[buf][l * 32 + s];
            float Cv  = sbc[buf][l * 32 + 16 + s];
            h = fmaf(__expf(dtv * Aval), h, (dtv * xiv) * Bv);
            float p = h * Cv;
            p += __shfl_xor_sync(0xffffffffu, p, 1);
            p += __shfl_xor_sync(0xffffffffu, p, 2);
            p += __shfl_xor_sync(0xffffffffu, p, 4);
            p += __shfl_xor_sync(0xffffffffu, p, 8);
            if (s == 0) {
                float zv = szt[buf][l * SCH + ch];
                float y = p + xiv * Dd;
                y *= zv / (1.f + __expf(-zv));
                sy[l * SCH + ch] = rnd_tf32(y);
            }
        }
        __syncthreads();

        *reinterpret_cast<float4*>(&g_y[dir][mbase + c * SLC + ll][d0 + lc4]) =
            *reinterpret_cast<const float4*>(&sy[ll * SCH + lc4]);
        if (c + 2 < NCHUNK) { load(c + 2, buf); CP_COMMIT(); }
    }
}

// ---------------- combine + layernorm + residual ----------------------------
__global__ void combine_ln_kernel(const float* __restrict__ x,
                                  const float* __restrict__ lng,
                                  const float* __restrict__ lnb,
                                  float* __restrict__ out)
{
    int row = blockIdx.x;
    int b = row / SEQ, l = row % SEQ;
    int rrev = b * SEQ + (SEQ - 1 - l);
    int tid = threadIdx.x;

    float v[4];
    float sum = 0.f, sq = 0.f;
#pragma unroll
    for (int i = 0; i < 4; i++) {
        int dm = tid + i * 256;
        float dv = 0.5f * (g_o[0][row][dm] + g_o[1][rrev][dm]);
        v[i] = dv;
        sum += dv;
        sq  += dv * dv;
    }
#pragma unroll
    for (int o = 16; o; o >>= 1) {
        sum += __shfl_xor_sync(0xffffffffu, sum, o);
        sq  += __shfl_xor_sync(0xffffffffu, sq,  o);
    }
    __shared__ float ssum[8], ssq[8];
    if ((tid & 31) == 0) { ssum[tid >> 5] = sum; ssq[tid >> 5] = sq; }
    __syncthreads();
    float ts = 0.f, tq = 0.f;
#pragma unroll
    for (int i = 0; i < 8; i++) { ts += ssum[i]; tq += ssq[i]; }
    float mu  = ts * (1.f / DMODEL);
    float var = tq * (1.f / DMODEL) - mu * mu;
    float inv = rsqrtf(var + 1e-5f);
#pragma unroll
    for (int i = 0; i < 4; i++) {
        int dm = tid + i * 256;
        out[(size_t)row * DMODEL + dm] =
            fmaf((v[i] - mu) * inv, lng[dm], lnb[dm]) + x[(size_t)row * DMODEL + dm];
    }
}

// ---------------- launch ----------------------------------------------------
extern "C" void kernel_launch(void* const* d_in, const int* in_sizes, int n_in,
                              void* d_out, int out_size)
{
    const float* x = (const float*)d_in[0];
    const float* in_proj[2] = {(const float*)d_in[1],  (const float*)d_in[10]};
    const float* conv_w [2] = {(const float*)d_in[2],  (const float*)d_in[11]};
    const float* conv_b [2] = {(const float*)d_in[3],  (const float*)d_in[12]};
    const float* x_proj [2] = {(const float*)d_in[4],  (const float*)d_in[13]};
    const float* dt_w   [2] = {(const float*)d_in[5],  (const float*)d_in[14]};
    const float* dt_b   [2] = {(const float*)d_in[6],  (const float*)d_in[15]};
    const float* A_log  [2] = {(const float*)d_in[7],  (const float*)d_in[16]};
    const float* Dp     [2] = {(const float*)d_in[8],  (const float*)d_in[17]};
    const float* out_pr [2] = {(const float*)d_in[9],  (const float*)d_in[18]};
    const float* ln_g = (const float*)d_in[19];
    const float* ln_b = (const float*)d_in[20];
    float* out = (float*)d_out;

    float *p_xz, *p_xi, *p_dbc, *p_dt, *p_y, *p_o, *p_xpart;
    float *p_rx, *p_rin, *p_rxp, *p_rdt, *p_rout;
    cudaGetSymbolAddress((void**)&p_xz,   g_xz);
    cudaGetSymbolAddress((void**)&p_xi,   g_xi);
    cudaGetSymbolAddress((void**)&p_dbc,  g_dbc);
    cudaGetSymbolAddress((void**)&p_dt,   g_dt);
    cudaGetSymbolAddress((void**)&p_y,    g_y);
    cudaGetSymbolAddress((void**)&p_o,    g_o);
    cudaGetSymbolAddress((void**)&p_xpart,g_xpart);
    cudaGetSymbolAddress((void**)&p_rx,   g_rx);
    cudaGetSymbolAddress((void**)&p_rin,  g_rw_in);
    cudaGetSymbolAddress((void**)&p_rxp,  g_rw_xp);
    cudaGetSymbolAddress((void**)&p_rdt,  g_rw_dt);
    cudaGetSymbolAddress((void**)&p_rout, g_rw_out);

    // smem opt-in per instantiation
    cudaFuncSetAttribute(gemm_mma<4,0,0>, cudaFuncAttributeMaxDynamicSharedMemorySize, GEMM_SMEM(4));
    cudaFuncSetAttribute(gemm_mma<4,1,0>, cudaFuncAttributeMaxDynamicSharedMemorySize, GEMM_SMEM(4));
    cudaFuncSetAttribute(gemm_mma<2,0,0>, cudaFuncAttributeMaxDynamicSharedMemorySize, GEMM_SMEM(2));
    cudaFuncSetAttribute(gemm_mma<2,2,0>, cudaFuncAttributeMaxDynamicSharedMemorySize, GEMM_SMEM(2));

    const size_t szXI  = (size_t)MROWS * DINNER;
    const size_t szXZ  = (size_t)MROWS * 2 * DINNER;
    const size_t szO   = (size_t)MROWS * DMODEL;

    // 0) tf32-pre-round x + all GEMM weights
    round_prepass<<<(RND_TOTAL / 4 + 255) / 256, 256>>>(
        x, in_proj[0], in_proj[1], x_proj[0], x_proj[1],
        dt_w[0], dt_w[1], out_pr[0], out_pr[1]);

    // 1) in_proj (big tile; dir1 reads x time-reversed): [2048 x 4096], K=1024
    gemm_mma<4,0,0><<<dim3(2 * DINNER / GEMM_BN, MROWS / 256, 2), 256, GEMM_SMEM(4)>>>(
        p_rx, 0, p_rin, p_rin + SZ_IN, p_xz, szXZ,
        MROWS, 2 * DINNER, DMODEL, DMODEL, DMODEL, 2 * DINNER,
        /*reverse_mask=*/2, /*nsplit=*/1, nullptr, nullptr);

    // 2) depthwise conv + silu
    conv_silu_kernel<<<(2 * MROWS * DINNER + 255) / 256, 256>>>(
        conv_w[0], conv_b[0], conv_w[1], conv_b[1]);

    // 3) x_proj split-K 8-way (small tile): [2048 x 96], K=2048 -> 8 x 256
    gemm_mma<2,0,0><<<dim3(1, MROWS / 128, 16), 256, GEMM_SMEM(2)>>>(
        p_xi, szXI, p_rxp, p_rxp + SZ_XP, p_xpart, (size_t)MROWS * 96,
        MROWS, 96, /*K=*/256, DINNER, DINNER, 96,
        0, /*nsplit=*/8, nullptr, nullptr);
    reduce_xpart<<<(2 * MROWS * 96 / 4 + 255) / 256, 256>>>();

    // 4) dt + softplus (small tile): [2048 x 2048], K=64 (A = dbc, lda=96)
    gemm_mma<2,2,0><<<dim3(DINNER / GEMM_BN, MROWS / 128, 2), 256, GEMM_SMEM(2)>>>(
        p_dbc, (size_t)MROWS * 96, p_rdt, p_rdt + SZ_DT, p_dt, szXI,
        MROWS, DINNER, DTRANK, 96, DTRANK, DINNER,
        0, 1, dt_b[0], dt_b[1]);

    // 5) selective scan (smem-staged)
    scan_kernel<<<2 * BATCHN * (DINNER / SCH), 256>>>(
        A_log[0], Dp[0], A_log[1], Dp[1]);

    // 6) out_proj + sigmoid (big tile): [2048 x 1024], K=2048
    gemm_mma<4,1,0><<<dim3(DMODEL / GEMM_BN, MROWS / 256, 2), 256, GEMM_SMEM(4)>>>(
        p_y, szXI, p_rout, p_rout + SZ_OUT, p_o, szO,
        MROWS, DMODEL, DINNER, DINNER, DINNER, DMODEL,
        0, 1, nullptr, nullptr);

    // 7) combine + layernorm + residual
    combine_ln_kernel<<<MROWS, 256>>>(x, ln_g, ln_b, out);
}

// round 13
// speedup vs baseline: 1.1698x; 1.0716x over previous
#include <cuda_runtime.h>
#include <math.h>
#include <stdint.h>

#define BATCHN 2
#define SEQ    1024
#define DMODEL 1024
#define DINNER 2048
#define DSTATE 16
#define DCONV  4
#define DTRANK 64
#define MROWS  (BATCHN * SEQ)   // 2048

// ---------------- scratch (device globals; no allocation allowed) -----------
__device__ float g_xz [2][MROWS][2 * DINNER];   // in_proj output
__device__ float g_xi [2][MROWS][DINNER];       // conv+silu output (tf32-pre-rounded)
__device__ float g_dbc[2][MROWS][96];           // x_proj output (tf32-pre-rounded)
__device__ float g_dt [2][MROWS][DINNER];       // softplus(dt)
__device__ float g_y  [2][MROWS][DINNER];       // scan output (tf32-pre-rounded)
__device__ float g_o  [2][MROWS][DMODEL];       // sigmoid(out_proj)
__device__ float g_xpart[16][MROWS * 96];       // x_proj split-K partials

// round for tf32: truncate(v + 0x1000) == round-half-away(v) for HMMA.TF32.
#define TF32_RND 0x1000u
__device__ __forceinline__ float rnd_tf32(float f) {
    return __uint_as_float(__float_as_uint(f) + TF32_RND);
}

__device__ __forceinline__ void cp16(uint32_t dst, const float* src, int bytes) {
    asm volatile("cp.async.ca.shared.global [%0], [%1], 16, %2;"
                 :: "r"(dst), "l"(src), "r"(bytes));
}
#define CP_COMMIT() asm volatile("cp.async.commit_group;" ::: "memory")

// ---------------- tf32 tensor-core GEMM (cp.async double-buffered) ----------
//  C[M,N] = A[M,K_chunk] * W[N,K_chunk]^T
// z = dir * nsplit + part; part selects K chunk (split-K); dir selects weights.
// EPI: 0 none, 1 sigmoid, 2 softplus(v+bias[n]);  ROUND: tf32-round output
// RNDA/RNDB: round A/B fragments to tf32 in the mainloop (for operands not
// pre-rounded in memory). reverse_mask bit dir: time-flip A rows.
// M%128==0, K%32==0, K/32>=2; N ragged OK.  (Exact R7 tile config.)
#define GEMM_BM 128
#define GEMM_BN 128
#define GEMM_BK 32
#define GEMM_LDS 40
#define GEMM_SMEM_BYTES (4 * GEMM_BM * GEMM_LDS * 4)   // 81920

template<int EPI, int ROUND, int RNDA, int RNDB>
__global__ __launch_bounds__(256, 2)
void gemm_mma(const float* __restrict__ A0, size_t strideA,
              const float* __restrict__ W0, const float* __restrict__ W1,
              float* __restrict__ C0, size_t strideC,
              int M, int N, int K, int lda, int ldw, int ldc,
              int reverse_mask, int nsplit,
              const float* __restrict__ bias0, const float* __restrict__ bias1)
{
    constexpr int LDS_S = GEMM_LDS;
    extern __shared__ uint32_t smem[];
    uint32_t* Asb[2] = { smem,                           smem + GEMM_BM * LDS_S };
    uint32_t* Bsb[2] = { smem + 2 * GEMM_BM * LDS_S,
                         smem + 2 * GEMM_BM * LDS_S + GEMM_BN * LDS_S };

    const int z    = blockIdx.z;
    const int dir  = z / nsplit;
    const int part = z - dir * nsplit;
    const float* A = A0 + (size_t)dir * strideA + (size_t)part * K;
    const float* W = (dir ? W1 : W0) + (size_t)part * K;
    float* C = C0 + (size_t)z * strideC;
    const float* bias = (EPI == 2) ? (dir ? bias1 : bias0) : nullptr;
    const int reverse = (reverse_mask >> dir) & 1;

    const int tid  = threadIdx.x;
    const int lane = tid & 31;
    const int wid  = tid >> 5;
    const int wm   = wid >> 1;                   // 0..3  warp row (32 rows)
    const int wn   = wid & 1;                    // 0..1  warp col (64 cols)
    const int m0   = blockIdx.y * GEMM_BM;
    const int n0   = blockIdx.x * GEMM_BN;
    const int lq = lane >> 2;
    const int lr = lane & 3;

    const int fr  = tid >> 3;                    // fill row base (0..31)
    const int fc  = tid & 7;                     // fill 16B chunk

    float acc[2][8][4];
#pragma unroll
    for (int i = 0; i < 2; i++)
#pragma unroll
        for (int j = 0; j < 8; j++)
#pragma unroll
            for (int c = 0; c < 4; c++) acc[i][j][c] = 0.f;

    const int KT = K / GEMM_BK;

    auto fill = [&](int kt, int buf) {
        int k0 = kt * GEMM_BK;
        uint32_t abuf = (uint32_t)__cvta_generic_to_shared(Asb[buf]);
        uint32_t bbuf = (uint32_t)__cvta_generic_to_shared(Bsb[buf]);
#pragma unroll
        for (int i = 0; i < 4; i++) {
            int r = fr + i * 32;
            int m = m0 + r;
            int mrow = m;
            if (reverse) mrow = (m & ~(SEQ - 1)) + (SEQ - 1 - (m & (SEQ - 1)));
            cp16(abuf + (r * LDS_S + fc * 4) * 4, &A[(size_t)mrow * lda + k0 + fc * 4], 16);
            int n = n0 + r;
            const float* bs = &W[(size_t)(n < N ? n : 0) * ldw + k0 + fc * 4];
            cp16(bbuf + (r * LDS_S + fc * 4) * 4, bs, (n < N) ? 16 : 0);
        }
    };

    fill(0, 0);
    CP_COMMIT();

    for (int kt = 0; kt < KT; kt++) {
        const int cur = kt & 1;
        if (kt + 1 < KT) {
            fill(kt + 1, cur ^ 1);
            CP_COMMIT();
            asm volatile("cp.async.wait_group 1;");
        } else {
            asm volatile("cp.async.wait_group 0;");
        }
        __syncthreads();

        const uint32_t* Ac = Asb[cur];
        const uint32_t* Bc = Bsb[cur];
        // k-slot relabeling: slot lr <- logical k 2lr, slot lr+4 <- 2lr+1 for
        // both A and B -> dot product reordered only; pairs adjacent -> LDS.64.
#pragma unroll
        for (int ks = 0; ks < 4; ks++) {
            const int k = ks * 8 + 2 * lr;
            uint2 afp[2][2];
#pragma unroll
            for (int i = 0; i < 2; i++) {
                int mr = wm * 32 + i * 16 + lq;
                afp[i][0] = *reinterpret_cast<const uint2*>(&Ac[ mr      * LDS_S + k]);
                afp[i][1] = *reinterpret_cast<const uint2*>(&Ac[(mr + 8) * LDS_S + k]);
                if (RNDA) {
                    afp[i][0].x += TF32_RND; afp[i][0].y += TF32_RND;
                    afp[i][1].x += TF32_RND; afp[i][1].y += TF32_RND;
                }
            }
#pragma unroll
            for (int j = 0; j < 8; j++) {
                int nr = wn * 64 + j * 8 + lq;
                uint2 bfp = *reinterpret_cast<const uint2*>(&Bc[nr * LDS_S + k]);
                if (RNDB) { bfp.x += TF32_RND; bfp.y += TF32_RND; }
#pragma unroll
                for (int i = 0; i < 2; i++) {
                    asm volatile(
                        "mma.sync.aligned.m16n8k8.row.col.f32.tf32.tf32.f32 "
                        "{%0,%1,%2,%3}, {%4,%5,%6,%7}, {%8,%9}, {%0,%1,%2,%3};"
                        : "+f"(acc[i][j][0]), "+f"(acc[i][j][1]),
                          "+f"(acc[i][j][2]), "+f"(acc[i][j][3])
                        : "r"(afp[i][0].x), "r"(afp[i][1].x),
                          "r"(afp[i][0].y), "r"(afp[i][1].y),
                          "r"(bfp.x), "r"(bfp.y));
                }
            }
        }
        __syncthreads();
    }

    // ---- epilogue ----
#pragma unroll
    for (int i = 0; i < 2; i++) {
        int mrow0 = m0 + wm * 32 + i * 16 + lq;
#pragma unroll
        for (int j = 0; j < 8; j++) {
            int n = n0 + wn * 64 + j * 8 + lr * 2;
            if (n >= N) continue;
#pragma unroll
            for (int half = 0; half < 2; half++) {
                int m = mrow0 + half * 8;
                float v0 = acc[i][j][half * 2 + 0];
                float v1 = acc[i][j][half * 2 + 1];
                if (EPI == 1) {
                    v0 = 1.f / (1.f + __expf(-v0));
                    v1 = 1.f / (1.f + __expf(-v1));
                } else if (EPI == 2) {
                    v0 += bias[n];
                    v1 += bias[n + 1];
                    v0 = fmaxf(v0, 0.f) + log1pf(__expf(-fabsf(v0)));
                    v1 = fmaxf(v1, 0.f) + log1pf(__expf(-fabsf(v1)));
                }
                if (ROUND) { v0 = rnd_tf32(v0); v1 = rnd_tf32(v1); }
                *reinterpret_cast<float2*>(&C[(size_t)m * ldc + n]) = make_float2(v0, v1);
            }
        }
    }
}

// ---------------- split-K reduction for x_proj ------------------------------
__global__ void reduce_xpart()
{
    int f = blockIdx.x * blockDim.x + threadIdx.x;   // float4 index
    int e = f * 4;
    if (e >= 2 * MROWS * 96) return;
    int dir = e / (MROWS * 96);
    int r   = e - dir * (MROWS * 96);
    float4 acc = make_float4(0.f, 0.f, 0.f, 0.f);
#pragma unroll
    for (int part = 0; part < 8; part++) {
        float4 v = *reinterpret_cast<const float4*>(&g_xpart[dir * 8 + part][r]);
        acc.x += v.x; acc.y += v.y; acc.z += v.z; acc.w += v.w;
    }
    acc.x = rnd_tf32(acc.x); acc.y = rnd_tf32(acc.y);
    acc.z = rnd_tf32(acc.z); acc.w = rnd_tf32(acc.w);
    *reinterpret_cast<float4*>(&g_dbc[dir][0][0] + r) = acc;
}

// ---------------- depthwise causal conv (k=4) + silu, both dirs -------------
__global__ void conv_silu_kernel(const float* __restrict__ cw0, const float* __restrict__ cb0,
                                 const float* __restrict__ cw1, const float* __restrict__ cb1)
{
    int idx = blockIdx.x * blockDim.x + threadIdx.x;
    if (idx >= 2 * MROWS * DINNER) return;
    int c = idx % DINNER;
    int m = (idx / DINNER) % MROWS;
    int dir = idx / (MROWS * DINNER);
    const float* cw = dir ? cw1 : cw0;
    const float* cb = dir ? cb1 : cb0;
    int l = m & (SEQ - 1);
    int mb = m - l;
    float acc = cb[c];
#pragma unroll
    for (int k = 0; k < DCONV; k++) {
        int ls = l - (DCONV - 1) + k;
        if (ls >= 0) acc = fmaf(g_xz[dir][mb + ls][c], cw[c * DCONV + k], acc);
    }
    g_xi[dir][m][c] = rnd_tf32(acc / (1.f + __expf(-acc)));
}

// ---------------- selective scan: smem-staged chunks ------------------------
// block = 16 channels of one (dir, batch); 256 threads = 16 ch x 16 states.
#define SCH 16
#define SLC 64
#define NCHUNK (SEQ / SLC)
__global__ __launch_bounds__(256)
void scan_kernel(const float* __restrict__ Alog0, const float* __restrict__ D0,
                 const float* __restrict__ Alog1, const float* __restrict__ D1)
{
    __shared__ float sdt[2][SLC * SCH];
    __shared__ float sxi[2][SLC * SCH];
    __shared__ float szt[2][SLC * SCH];
    __shared__ float sbc[2][SLC * 32];
    __shared__ float sy [SLC * SCH];

    const int nCg = DINNER / SCH;                 // 128
    const int bid = blockIdx.x;
    const int dir = bid / (BATCHN * nCg);
    const int rem = bid % (BATCHN * nCg);
    const int b   = rem / nCg;
    const int cg  = rem % nCg;
    const int d0  = cg * SCH;
    const int tid = threadIdx.x;
    const int ch  = tid >> 4;
    const int s   = tid & 15;
    const int d   = d0 + ch;
    const int mbase = b * SEQ;

    const float* Alog = dir ? Alog1 : Alog0;
    const float* Dp   = dir ? D1    : D0;
    const float Aval = -__expf(Alog[d * DSTATE + s]);
    const float Dd   = Dp[d];

    const int ll  = tid >> 2;                     // 0..63
    const int lc4 = (tid & 3) * 4;                // 0,4,8,12

    auto load = [&](int c, int buf) {
        int m = mbase + c * SLC;
        cp16((uint32_t)__cvta_generic_to_shared(&sdt[buf][0]) + tid * 16,
             &g_dt[dir][m + ll][d0 + lc4], 16);
        cp16((uint32_t)__cvta_generic_to_shared(&sxi[buf][0]) + tid * 16,
             &g_xi[dir][m + ll][d0 + lc4], 16);
        cp16((uint32_t)__cvta_generic_to_shared(&szt[buf][0]) + tid * 16,
             &g_xz[dir][m + ll][DINNER + d0 + lc4], 16);
#pragma unroll
        for (int i = 0; i < 2; i++) {
            int f = tid + i * 256;
            int l = f >> 3, c4 = (f & 7) * 4;
            cp16((uint32_t)__cvta_generic_to_shared(&sbc[buf][0]) + f * 16,
                 &g_dbc[dir][m + l][DTRANK + c4], 16);
        }
    };

    load(0, 0); CP_COMMIT();
    load(1, 1); CP_COMMIT();

    float h = 0.f;
    for (int c = 0; c < NCHUNK; c++) {
        const int buf = c & 1;
        if (c + 1 < NCHUNK) asm volatile("cp.async.wait_group 1;");
        else                asm volatile("cp.async.wait_group 0;");
        __syncthreads();

#pragma unroll 4
        for (int l = 0; l < SLC; l++) {
            float dtv = sdt[buf][l * SCH + ch];
            float xiv = sxi[buf][l * SCH + ch];
            float Bv  = sbc[buf][l * 32 + s];
            float Cv  = sbc[buf][l * 32 + 16 + s];
            h = fmaf(__expf(dtv * Aval), h, (dtv * xiv) * Bv);
            float p = h * Cv;
            p += __shfl_xor_sync(0xffffffffu, p, 1);
            p += __shfl_xor_sync(0xffffffffu, p, 2);
            p += __shfl_xor_sync(0xffffffffu, p, 4);
            p += __shfl_xor_sync(0xffffffffu, p, 8);
            if (s == 0) {
                float zv = szt[buf][l * SCH + ch];
                float y = p + xiv * Dd;
                y *= zv / (1.f + __expf(-zv));
                sy[l * SCH + ch] = rnd_tf32(y);
            }
        }
        __syncthreads();

        *reinterpret_cast<float4*>(&g_y[dir][mbase + c * SLC + ll][d0 + lc4]) =
            *reinterpret_cast<const float4*>(&sy[ll * SCH + lc4]);
        if (c + 2 < NCHUNK) { load(c + 2, buf); CP_COMMIT(); }
    }
}

// ---------------- combine + layernorm + residual ----------------------------
__global__ void combine_ln_kernel(const float* __restrict__ x,
                                  const float* __restrict__ lng,
                                  const float* __restrict__ lnb,
                                  float* __restrict__ out)
{
    int row = blockIdx.x;
    int b = row / SEQ, l = row % SEQ;
    int rrev = b * SEQ + (SEQ - 1 - l);
    int tid = threadIdx.x;

    float v[4];
    float sum = 0.f, sq = 0.f;
#pragma unroll
    for (int i = 0; i < 4; i++) {
        int dm = tid + i * 256;
        float dv = 0.5f * (g_o[0][row][dm] + g_o[1][rrev][dm]);
        v[i] = dv;
        sum += dv;
        sq  += dv * dv;
    }
#pragma unroll
    for (int o = 16; o; o >>= 1) {
        sum += __shfl_xor_sync(0xffffffffu, sum, o);
        sq  += __shfl_xor_sync(0xffffffffu, sq,  o);
    }
    __shared__ float ssum[8], ssq[8];
    if ((tid & 31) == 0) { ssum[tid >> 5] = sum; ssq[tid >> 5] = sq; }
    __syncthreads();
    float ts = 0.f, tq = 0.f;
#pragma unroll
    for (int i = 0; i < 8; i++) { ts += ssum[i]; tq += ssq[i]; }
    float mu  = ts * (1.f / DMODEL);
    float var = tq * (1.f / DMODEL) - mu * mu;
    float inv = rsqrtf(var + 1e-5f);
#pragma unroll
    for (int i = 0; i < 4; i++) {
        int dm = tid + i * 256;
        out[(size_t)row * DMODEL + dm] =
            fmaf((v[i] - mu) * inv, lng[dm], lnb[dm]) + x[(size_t)row * DMODEL + dm];
    }
}

// ---------------- launch ----------------------------------------------------
extern "C" void kernel_launch(void* const* d_in, const int* in_sizes, int n_in,
                              void* d_out, int out_size)
{
    const float* x = (const float*)d_in[0];
    const float* in_proj[2] = {(const float*)d_in[1],  (const float*)d_in[10]};
    const float* conv_w [2] = {(const float*)d_in[2],  (const float*)d_in[11]};
    const float* conv_b [2] = {(const float*)d_in[3],  (const float*)d_in[12]};
    const float* x_proj [2] = {(const float*)d_in[4],  (const float*)d_in[13]};
    const float* dt_w   [2] = {(const float*)d_in[5],  (const float*)d_in[14]};
    const float* dt_b   [2] = {(const float*)d_in[6],  (const float*)d_in[15]};
    const float* A_log  [2] = {(const float*)d_in[7],  (const float*)d_in[16]};
    const float* Dp     [2] = {(const float*)d_in[8],  (const float*)d_in[17]};
    const float* out_pr [2] = {(const float*)d_in[9],  (const float*)d_in[18]};
    const float* ln_g = (const float*)d_in[19];
    const float* ln_b = (const float*)d_in[20];
    float* out = (float*)d_out;

    float *p_xz, *p_xi, *p_dbc, *p_dt, *p_y, *p_o, *p_xpart;
    cudaGetSymbolAddress((void**)&p_xz,   g_xz);
    cudaGetSymbolAddress((void**)&p_xi,   g_xi);
    cudaGetSymbolAddress((void**)&p_dbc,  g_dbc);
    cudaGetSymbolAddress((void**)&p_dt,   g_dt);
    cudaGetSymbolAddress((void**)&p_y,    g_y);
    cudaGetSymbolAddress((void**)&p_o,    g_o);
    cudaGetSymbolAddress((void**)&p_xpart,g_xpart);

    cudaFuncSetAttribute(gemm_mma<0,0,1,1>, cudaFuncAttributeMaxDynamicSharedMemorySize, GEMM_SMEM_BYTES);
    cudaFuncSetAttribute(gemm_mma<0,0,0,1>, cudaFuncAttributeMaxDynamicSharedMemorySize, GEMM_SMEM_BYTES);
    cudaFuncSetAttribute(gemm_mma<2,0,0,1>, cudaFuncAttributeMaxDynamicSharedMemorySize, GEMM_SMEM_BYTES);
    cudaFuncSetAttribute(gemm_mma<1,0,0,1>, cudaFuncAttributeMaxDynamicSharedMemorySize, GEMM_SMEM_BYTES);

    const size_t szXZ  = (size_t)MROWS * 2 * DINNER;
    const size_t szXI  = (size_t)MROWS * DINNER;
    const size_t szO   = (size_t)MROWS * DMODEL;

    // 1) in_proj (A=x raw -> RNDA, weights raw -> RNDB): [2048 x 4096], K=1024
    gemm_mma<0,0,1,1><<<dim3(2 * DINNER / 128, MROWS / 128, 2), 256, GEMM_SMEM_BYTES>>>(
        x, 0, in_proj[0], in_proj[1], p_xz, szXZ,
        MROWS, 2 * DINNER, DMODEL, DMODEL, DMODEL, 2 * DINNER,
        /*reverse_mask=*/2, /*nsplit=*/1, nullptr, nullptr);

    // 2) depthwise conv + silu (output tf32-pre-rounded)
    conv_silu_kernel<<<(2 * MROWS * DINNER + 255) / 256, 256>>>(
        conv_w[0], conv_b[0], conv_w[1], conv_b[1]);

    // 3) x_proj split-K 8-way (A=xi pre-rounded, W raw): [2048 x 96], K=8x256
    gemm_mma<0,0,0,1><<<dim3(1, MROWS / 128, 16), 256, GEMM_SMEM_BYTES>>>(
        p_xi, szXI, x_proj[0], x_proj[1], p_xpart, (size_t)MROWS * 96,
        MROWS, 96, /*K=*/256, DINNER, DINNER, 96,
        0, /*nsplit=*/8, nullptr, nullptr);
    reduce_xpart<<<(2 * MROWS * 96 / 4 + 255) / 256, 256>>>();

    // 4) dt + softplus (A=dbc pre-rounded, W raw): [2048 x 2048], K=64
    gemm_mma<2,0,0,1><<<dim3(DINNER / 128, MROWS / 128, 2), 256, GEMM_SMEM_BYTES>>>(
        p_dbc, (size_t)MROWS * 96, dt_w[0], dt_w[1], p_dt, szXI,
        MROWS, DINNER, DTRANK, 96, DTRANK, DINNER,
        0, 1, dt_b[0], dt_b[1]);

    // 5) selective scan (smem-staged, output pre-rounded)
    scan_kernel<<<2 * BATCHN * (DINNER / SCH), 256>>>(
        A_log[0], Dp[0], A_log[1], Dp[1]);

    // 6) out_proj + sigmoid (A=y pre-rounded, W raw): [2048 x 1024], K=2048
    gemm_mma<1,0,0,1><<<dim3(DMODEL / 128, MROWS / 128, 2), 256, GEMM_SMEM_BYTES>>>(
        p_y, szXI, out_pr[0], out_pr[1], p_o, szO,
        MROWS, DMODEL, DINNER, DINNER, DINNER, DMODEL,
        0, 1, nullptr, nullptr);

    // 7) combine + layernorm + residual
    combine_ln_kernel<<<MROWS, 256>>>(x, ln_g, ln_b, out);
}

// round 14
// speedup vs baseline: 1.2058x; 1.0308x over previous
#include <cuda_runtime.h>
#include <math.h>
#include <stdint.h>

#define BATCHN 2
#define SEQ    1024
#define DMODEL 1024
#define DINNER 2048
#define DSTATE 16
#define DCONV  4
#define DTRANK 64
#define MROWS  (BATCHN * SEQ)   // 2048

// ---------------- scratch (device globals; no allocation allowed) -----------
__device__ float g_xz [2][MROWS][2 * DINNER];   // in_proj output
__device__ float g_xi [2][MROWS][DINNER];       // conv+silu output (tf32-pre-rounded)
__device__ float g_dbc[2][MROWS][96];           // x_proj output (tf32-pre-rounded)
__device__ float g_dt [2][MROWS][DINNER];       // softplus(dt)
__device__ float g_y  [2][MROWS][DINNER];       // scan output (tf32-pre-rounded)
__device__ float g_o  [2][MROWS][DMODEL];       // sigmoid(out_proj)
__device__ float g_xpart[16][MROWS * 96];       // x_proj split-K partials

// round for tf32: truncate(v + 0x1000) == round-half-away(v) for HMMA.TF32.
#define TF32_RND 0x1000u
__device__ __forceinline__ float rnd_tf32(float f) {
    return __uint_as_float(__float_as_uint(f) + TF32_RND);
}

__device__ __forceinline__ void cp16(uint32_t dst, const float* src, int bytes) {
    asm volatile("cp.async.ca.shared.global [%0], [%1], 16, %2;"
                 :: "r"(dst), "l"(src), "r"(bytes));
}
#define CP_COMMIT() asm volatile("cp.async.commit_group;" ::: "memory")

// ---------------- tf32 tensor-core GEMM (cp.async, single-sync loop) --------
//  C[M,N] = A[M,K_chunk] * W[N,K_chunk]^T
// z = dir * nsplit + part; part selects K chunk (split-K); dir selects weights.
// EPI: 0 none, 1 sigmoid, 2 softplus(v+bias[n]);  ROUND: tf32-round output
// RNDA/RNDB: round A/B fragments to tf32 in the mainloop.
// reverse_mask bit dir: time-flip A rows. M%128==0, K%32==0, K/32>=2.
#define GEMM_BM 128
#define GEMM_BN 128
#define GEMM_BK 32
#define GEMM_LDS 40
#define GEMM_SMEM_BYTES (4 * GEMM_BM * GEMM_LDS * 4)   // 81920

template<int EPI, int ROUND, int RNDA, int RNDB>
__global__ __launch_bounds__(256, 2)
void gemm_mma(const float* __restrict__ A0, size_t strideA,
              const float* __restrict__ W0, const float* __restrict__ W1,
              float* __restrict__ C0, size_t strideC,
              int M, int N, int K, int lda, int ldw, int ldc,
              int reverse_mask, int nsplit,
              const float* __restrict__ bias0, const float* __restrict__ bias1)
{
    constexpr int LDS_S = GEMM_LDS;
    extern __shared__ uint32_t smem[];
    uint32_t* Asb[2] = { smem,                           smem + GEMM_BM * LDS_S };
    uint32_t* Bsb[2] = { smem + 2 * GEMM_BM * LDS_S,
                         smem + 2 * GEMM_BM * LDS_S + GEMM_BN * LDS_S };

    const int z    = blockIdx.z;
    const int dir  = z / nsplit;
    const int part = z - dir * nsplit;
    const float* A = A0 + (size_t)dir * strideA + (size_t)part * K;
    const float* W = (dir ? W1 : W0) + (size_t)part * K;
    float* C = C0 + (size_t)z * strideC;
    const float* bias = (EPI == 2) ? (dir ? bias1 : bias0) : nullptr;
    const int reverse = (reverse_mask >> dir) & 1;

    const int tid  = threadIdx.x;
    const int lane = tid & 31;
    const int wid  = tid >> 5;
    const int wm   = wid >> 1;                   // 0..3  warp row (32 rows)
    const int wn   = wid & 1;                    // 0..1  warp col (64 cols)
    const int m0   = blockIdx.y * GEMM_BM;
    const int n0   = blockIdx.x * GEMM_BN;
    const int lq = lane >> 2;
    const int lr = lane & 3;

    const int fr  = tid >> 3;                    // fill row base (0..31)
    const int fc  = tid & 7;                     // fill 16B chunk

    float acc[2][8][4];
#pragma unroll
    for (int i = 0; i < 2; i++)
#pragma unroll
        for (int j = 0; j < 8; j++)
#pragma unroll
            for (int c = 0; c < 4; c++) acc[i][j][c] = 0.f;

    const int KT = K / GEMM_BK;

    auto fill = [&](int kt, int buf) {
        int k0 = kt * GEMM_BK;
        uint32_t abuf = (uint32_t)__cvta_generic_to_shared(Asb[buf]);
        uint32_t bbuf = (uint32_t)__cvta_generic_to_shared(Bsb[buf]);
#pragma unroll
        for (int i = 0; i < 4; i++) {
            int r = fr + i * 32;
            int m = m0 + r;
            int mrow = m;
            if (reverse) mrow = (m & ~(SEQ - 1)) + (SEQ - 1 - (m & (SEQ - 1)));
            cp16(abuf + (r * LDS_S + fc * 4) * 4, &A[(size_t)mrow * lda + k0 + fc * 4], 16);
            int n = n0 + r;
            const float* bs = &W[(size_t)(n < N ? n : 0) * ldw + k0 + fc * 4];
            cp16(bbuf + (r * LDS_S + fc * 4) * 4, bs, (n < N) ? 16 : 0);
        }
    };

    fill(0, 0);
    CP_COMMIT();

    for (int kt = 0; kt < KT; kt++) {
        const int cur = kt & 1;
        // single-sync mainloop (validated in R12): wait for tile kt's fill,
        // one barrier (orders tile kt-1's readers before refilling cur^1),
        // then prefetch kt+1 overlapped with tile kt's MMAs.
        asm volatile("cp.async.wait_group 0;");
        __syncthreads();
        if (kt + 1 < KT) {
            fill(kt + 1, cur ^ 1);
            CP_COMMIT();
        }

        const uint32_t* Ac = Asb[cur];
        const uint32_t* Bc = Bsb[cur];
        // k-slot relabeling: slot lr <- logical k 2lr, slot lr+4 <- 2lr+1 for
        // both A and B -> dot product reordered only; pairs adjacent -> LDS.64.
#pragma unroll
        for (int ks = 0; ks < 4; ks++) {
            const int k = ks * 8 + 2 * lr;
            uint2 afp[2][2];
#pragma unroll
            for (int i = 0; i < 2; i++) {
                int mr = wm * 32 + i * 16 + lq;
                afp[i][0] = *reinterpret_cast<const uint2*>(&Ac[ mr      * LDS_S + k]);
                afp[i][1] = *reinterpret_cast<const uint2*>(&Ac[(mr + 8) * LDS_S + k]);
                if (RNDA) {
                    afp[i][0].x += TF32_RND; afp[i][0].y += TF32_RND;
                    afp[i][1].x += TF32_RND; afp[i][1].y += TF32_RND;
                }
            }
#pragma unroll
            for (int j = 0; j < 8; j++) {
                int nr = wn * 64 + j * 8 + lq;
                uint2 bfp = *reinterpret_cast<const uint2*>(&Bc[nr * LDS_S + k]);
                if (RNDB) { bfp.x += TF32_RND; bfp.y += TF32_RND; }
#pragma unroll
                for (int i = 0; i < 2; i++) {
                    asm volatile(
                        "mma.sync.aligned.m16n8k8.row.col.f32.tf32.tf32.f32 "
                        "{%0,%1,%2,%3}, {%4,%5,%6,%7}, {%8,%9}, {%0,%1,%2,%3};"
                        : "+f"(acc[i][j][0]), "+f"(acc[i][j][1]),
                          "+f"(acc[i][j][2]), "+f"(acc[i][j][3])
                        : "r"(afp[i][0].x), "r"(afp[i][1].x),
                          "r"(afp[i][0].y), "r"(afp[i][1].y),
                          "r"(bfp.x), "r"(bfp.y));
                }
            }
        }
    }

    // ---- epilogue ----
#pragma unroll
    for (int i = 0; i < 2; i++) {
        int mrow0 = m0 + wm * 32 + i * 16 + lq;
#pragma unroll
        for (int j = 0; j < 8; j++) {
            int n = n0 + wn * 64 + j * 8 + lr * 2;
            if (n >= N) continue;
#pragma unroll
            for (int half = 0; half < 2; half++) {
                int m = mrow0 + half * 8;
                float v0 = acc[i][j][half * 2 + 0];
                float v1 = acc[i][j][half * 2 + 1];
                if (EPI == 1) {
                    v0 = 1.f / (1.f + __expf(-v0));
                    v1 = 1.f / (1.f + __expf(-v1));
                } else if (EPI == 2) {
                    v0 += bias[n];
                    v1 += bias[n + 1];
                    v0 = fmaxf(v0, 0.f) + log1pf(__expf(-fabsf(v0)));
                    v1 = fmaxf(v1, 0.f) + log1pf(__expf(-fabsf(v1)));
                }
                if (ROUND) { v0 = rnd_tf32(v0); v1 = rnd_tf32(v1); }
                *reinterpret_cast<float2*>(&C[(size_t)m * ldc + n]) = make_float2(v0, v1);
            }
        }
    }
}

// ---------------- split-K reduction for x_proj ------------------------------
__global__ void reduce_xpart()
{
    int f = blockIdx.x * blockDim.x + threadIdx.x;   // float4 index
    int e = f * 4;
    if (e >= 2 * MROWS * 96) return;
    int dir = e / (MROWS * 96);
    int r   = e - dir * (MROWS * 96);
    float4 acc = make_float4(0.f, 0.f, 0.f, 0.f);
#pragma unroll
    for (int part = 0; part < 8; part++) {
        float4 v = *reinterpret_cast<const float4*>(&g_xpart[dir * 8 + part][r]);
        acc.x += v.x; acc.y += v.y; acc.z += v.z; acc.w += v.w;
    }
    acc.x = rnd_tf32(acc.x); acc.y = rnd_tf32(acc.y);
    acc.z = rnd_tf32(acc.z); acc.w = rnd_tf32(acc.w);
    *reinterpret_cast<float4*>(&g_dbc[dir][0][0] + r) = acc;
}

// ---------------- depthwise causal conv (k=4) + silu, sliding window --------
// thread = one channel, 16 consecutive timesteps; warp stays coalesced in c.
#define CONV_LB 16
__global__ __launch_bounds__(256)
void conv_silu_kernel(const float* __restrict__ cw0, const float* __restrict__ cb0,
                      const float* __restrict__ cw1, const float* __restrict__ cb1)
{
    const int c   = blockIdx.x * 256 + threadIdx.x;      // channel
    const int l0  = blockIdx.y * CONV_LB;                // timestep block
    const int dir = blockIdx.z >> 1;
    const int b   = blockIdx.z & 1;
    const int mb  = b * SEQ;

    const float* cw = dir ? cw1 : cw0;
    const float* cb = dir ? cb1 : cb0;
    const float w0 = cw[c * DCONV + 0];
    const float w1 = cw[c * DCONV + 1];
    const float w2 = cw[c * DCONV + 2];
    const float w3 = cw[c * DCONV + 3];
    const float bias = cb[c];

    // rolling window of the 3 previous inputs
    float h0 = (l0 >= 3) ? g_xz[dir][mb + l0 - 3][c] : 0.f;
    float h1 = (l0 >= 2) ? g_xz[dir][mb + l0 - 2][c] : 0.f;
    float h2 = (l0 >= 1) ? g_xz[dir][mb + l0 - 1][c] : 0.f;

#pragma unroll
    for (int i = 0; i < CONV_LB; i++) {
        int l = l0 + i;
        float xv = g_xz[dir][mb + l][c];
        // same accumulation order as before: bias + k0(l-3) + k1 + k2 + k3(l)
        float acc = bias;
        acc = fmaf(h0, w0, acc);
        acc = fmaf(h1, w1, acc);
        acc = fmaf(h2, w2, acc);
        acc = fmaf(xv, w3, acc);
        g_xi[dir][mb + l][c] = rnd_tf32(acc / (1.f + __expf(-acc)));
        h0 = h1; h1 = h2; h2 = xv;
    }
}

// ---------------- selective scan: smem-staged chunks ------------------------
// block = 16 channels of one (dir, batch); 256 threads = 16 ch x 16 states.
#define SCH 16
#define SLC 64
#define NCHUNK (SEQ / SLC)
__global__ __launch_bounds__(256)
void scan_kernel(const float* __restrict__ Alog0, const float* __restrict__ D0,
                 const float* __restrict__ Alog1, const float* __restrict__ D1)
{
    __shared__ float sdt[2][SLC * SCH];
    __shared__ float sxi[2][SLC * SCH];
    __shared__ float szt[2][SLC * SCH];
    __shared__ float sbc[2][SLC * 32];
    __shared__ float sy [SLC * SCH];

    const int nCg = DINNER / SCH;                 // 128
    const int bid = blockIdx.x;
    const int dir = bid / (BATCHN * nCg);
    const int rem = bid % (BATCHN * nCg);
    const int b   = rem / nCg;
    const int cg  = rem % nCg;
    const int d0  = cg * SCH;
    const int tid = threadIdx.x;
    const int ch  = tid >> 4;
    const int s   = tid & 15;
    const int d   = d0 + ch;
    const int mbase = b * SEQ;

    const float* Alog = dir ? Alog1 : Alog0;
    const float* Dp   = dir ? D1    : D0;
    const float Aval = -__expf(Alog[d * DSTATE + s]);
    const float Dd   = Dp[d];

    const int ll  = tid >> 2;                     // 0..63
    const int lc4 = (tid & 3) * 4;                // 0,4,8,12

    auto load = [&](int c, int buf) {
        int m = mbase + c * SLC;
        cp16((uint32_t)__cvta_generic_to_shared(&sdt[buf][0]) + tid * 16,
             &g_dt[dir][m + ll][d0 + lc4], 16);
        cp16((uint32_t)__cvta_generic_to_shared(&sxi[buf][0]) + tid * 16,
             &g_xi[dir][m + ll][d0 + lc4], 16);
        cp16((uint32_t)__cvta_generic_to_shared(&szt[buf][0]) + tid * 16,
             &g_xz[dir][m + ll][DINNER + d0 + lc4], 16);
#pragma unroll
        for (int i = 0; i < 2; i++) {
            int f = tid + i * 256;
            int l = f >> 3, c4 = (f & 7) * 4;
            cp16((uint32_t)__cvta_generic_to_shared(&sbc[buf][0]) + f * 16,
                 &g_dbc[dir][m + l][DTRANK + c4], 16);
        }
    };

    load(0, 0); CP_COMMIT();
    load(1, 1); CP_COMMIT();

    float h = 0.f;
    for (int c = 0; c < NCHUNK; c++) {
        const int buf = c & 1;
        if (c + 1 < NCHUNK) asm volatile("cp.async.wait_group 1;");
        else                asm volatile("cp.async.wait_group 0;");
        __syncthreads();

#pragma unroll 4
        for (int l = 0; l < SLC; l++) {
            float dtv = sdt[buf][l * SCH + ch];
            float xiv = sxi[buf][l * SCH + ch];
            float Bv  = sbc[buf][l * 32 + s];
            float Cv  = sbc[buf][l * 32 + 16 + s];
            h = fmaf(__expf(dtv * Aval), h, (dtv * xiv) * Bv);
            float p = h * Cv;
            p += __shfl_xor_sync(0xffffffffu, p, 1);
            p += __shfl_xor_sync(0xffffffffu, p, 2);
            p += __shfl_xor_sync(0xffffffffu, p, 4);
            p += __shfl_xor_sync(0xffffffffu, p, 8);
            if (s == 0) {
                float zv = szt[buf][l * SCH + ch];
                float y = p + xiv * Dd;
                y *= zv / (1.f + __expf(-zv));
                sy[l * SCH + ch] = rnd_tf32(y);
            }
        }
        __syncthreads();

        *reinterpret_cast<float4*>(&g_y[dir][mbase + c * SLC + ll][d0 + lc4]) =
            *reinterpret_cast<const float4*>(&sy[ll * SCH + lc4]);
        if (c + 2 < NCHUNK) { load(c + 2, buf); CP_COMMIT(); }
    }
}

// ---------------- combine + layernorm + residual ----------------------------
__global__ void combine_ln_kernel(const float* __restrict__ x,
                                  const float* __restrict__ lng,
                                  const float* __restrict__ lnb,
                                  float* __restrict__ out)
{
    int row = blockIdx.x;
    int b = row / SEQ, l = row % SEQ;
    int rrev = b * SEQ + (SEQ - 1 - l);
    int tid = threadIdx.x;

    float v[4];
    float sum = 0.f, sq = 0.f;
#pragma unroll
    for (int i = 0; i < 4; i++) {
        int dm = tid + i * 256;
        float dv = 0.5f * (g_o[0][row][dm] + g_o[1][rrev][dm]);
        v[i] = dv;
        sum += dv;
        sq  += dv * dv;
    }
#pragma unroll
    for (int o = 16; o; o >>= 1) {
        sum += __shfl_xor_sync(0xffffffffu, sum, o);
        sq  += __shfl_xor_sync(0xffffffffu, sq,  o);
    }
    __shared__ float ssum[8], ssq[8];
    if ((tid & 31) == 0) { ssum[tid >> 5] = sum; ssq[tid >> 5] = sq; }
    __syncthreads();
    float ts = 0.f, tq = 0.f;
#pragma unroll
    for (int i = 0; i < 8; i++) { ts += ssum[i]; tq += ssq[i]; }
    float mu  = ts * (1.f / DMODEL);
    float var = tq * (1.f / DMODEL) - mu * mu;
    float inv = rsqrtf(var + 1e-5f);
#pragma unroll
    for (int i = 0; i < 4; i++) {
        int dm = tid + i * 256;
        out[(size_t)row * DMODEL + dm] =
            fmaf((v[i] - mu) * inv, lng[dm], lnb[dm]) + x[(size_t)row * DMODEL + dm];
    }
}

// ---------------- launch ----------------------------------------------------
extern "C" void kernel_launch(void* const* d_in, const int* in_sizes, int n_in,
                              void* d_out, int out_size)
{
    const float* x = (const float*)d_in[0];
    const float* in_proj[2] = {(const float*)d_in[1],  (const float*)d_in[10]};
    const float* conv_w [2] = {(const float*)d_in[2],  (const float*)d_in[11]};
    const float* conv_b [2] = {(const float*)d_in[3],  (const float*)d_in[12]};
    const float* x_proj [2] = {(const float*)d_in[4],  (const float*)d_in[13]};
    const float* dt_w   [2] = {(const float*)d_in[5],  (const float*)d_in[14]};
    const float* dt_b   [2] = {(const float*)d_in[6],  (const float*)d_in[15]};
    const float* A_log  [2] = {(const float*)d_in[7],  (const float*)d_in[16]};
    const float* Dp     [2] = {(const float*)d_in[8],  (const float*)d_in[17]};
    const float* out_pr [2] = {(const float*)d_in[9],  (const float*)d_in[18]};
    const float* ln_g = (const float*)d_in[19];
    const float* ln_b = (const float*)d_in[20];
    float* out = (float*)d_out;

    float *p_xz, *p_xi, *p_dbc, *p_dt, *p_y, *p_o, *p_xpart;
    cudaGetSymbolAddress((void**)&p_xz,   g_xz);
    cudaGetSymbolAddress((void**)&p_xi,   g_xi);
    cudaGetSymbolAddress((void**)&p_dbc,  g_dbc);
    cudaGetSymbolAddress((void**)&p_dt,   g_dt);
    cudaGetSymbolAddress((void**)&p_y,    g_y);
    cudaGetSymbolAddress((void**)&p_o,    g_o);
    cudaGetSymbolAddress((void**)&p_xpart,g_xpart);

    cudaFuncSetAttribute(gemm_mma<0,0,1,1>, cudaFuncAttributeMaxDynamicSharedMemorySize, GEMM_SMEM_BYTES);
    cudaFuncSetAttribute(gemm_mma<0,0,0,1>, cudaFuncAttributeMaxDynamicSharedMemorySize, GEMM_SMEM_BYTES);
    cudaFuncSetAttribute(gemm_mma<2,0,0,1>, cudaFuncAttributeMaxDynamicSharedMemorySize, GEMM_SMEM_BYTES);
    cudaFuncSetAttribute(gemm_mma<1,0,0,1>, cudaFuncAttributeMaxDynamicSharedMemorySize, GEMM_SMEM_BYTES);

    const size_t szXZ  = (size_t)MROWS * 2 * DINNER;
    const size_t szXI  = (size_t)MROWS * DINNER;
    const size_t szO   = (size_t)MROWS * DMODEL;

    // 1) in_proj (A=x raw -> RNDA, weights raw -> RNDB): [2048 x 4096], K=1024
    gemm_mma<0,0,1,1><<<dim3(2 * DINNER / 128, MROWS / 128, 2), 256, GEMM_SMEM_BYTES>>>(
        x, 0, in_proj[0], in_proj[1], p_xz, szXZ,
        MROWS, 2 * DINNER, DMODEL, DMODEL, DMODEL, 2 * DINNER,
        /*reverse_mask=*/2, /*nsplit=*/1, nullptr, nullptr);

    // 2) depthwise conv + silu (sliding window, output tf32-pre-rounded)
    conv_silu_kernel<<<dim3(DINNER / 256, SEQ / CONV_LB, 2 * BATCHN), 256>>>(
        conv_w[0], conv_b[0], conv_w[1], conv_b[1]);

    // 3) x_proj split-K 8-way (A=xi pre-rounded, W raw): [2048 x 96], K=8x256
    gemm_mma<0,0,0,1><<<dim3(1, MROWS / 128, 16), 256, GEMM_SMEM_BYTES>>>(
        p_xi, szXI, x_proj[0], x_proj[1], p_xpart, (size_t)MROWS * 96,
        MROWS, 96, /*K=*/256, DINNER, DINNER, 96,
        0, /*nsplit=*/8, nullptr, nullptr);
    reduce_xpart<<<(2 * MROWS * 96 / 4 + 255) / 256, 256>>>();

    // 4) dt + softplus (A=dbc pre-rounded, W raw): [2048 x 2048], K=64
    gemm_mma<2,0,0,1><<<dim3(DINNER / 128, MROWS / 128, 2), 256, GEMM_SMEM_BYTES>>>(
        p_dbc, (size_t)MROWS * 96, dt_w[0], dt_w[1], p_dt, szXI,
        MROWS, DINNER, DTRANK, 96, DTRANK, DINNER,
        0, 1, dt_b[0], dt_b[1]);

    // 5) selective scan (smem-staged, output pre-rounded)
    scan_kernel<<<2 * BATCHN * (DINNER / SCH), 256>>>(
        A_log[0], Dp[0], A_log[1], Dp[1]);

    // 6) out_proj + sigmoid (A=y pre-rounded, W raw): [2048 x 1024], K=2048
    gemm_mma<1,0,0,1><<<dim3(DMODEL / 128, MROWS / 128, 2), 256, GEMM_SMEM_BYTES>>>(
        p_y, szXI, out_pr[0], out_pr[1], p_o, szO,
        MROWS, DMODEL, DINNER, DINNER, DINNER, DMODEL,
        0, 1, nullptr, nullptr);

    // 7) combine + layernorm + residual
    combine_ln_kernel<<<MROWS, 256>>>(x, ln_g, ln_b, out);
}